// round 11
// baseline (speedup 1.0000x reference)
#include <cuda_runtime.h>
#include <cuda_bf16.h>
#include <math.h>
#include <stdint.h>

#define TOKENS 16384
#define DDIM   2048
#define NEXP   64
#define HDIM   1024

// Output layout (float32): idx [16384*2] | scores [16384*2] | probs [16384*64] | imp [64] | load [64]
#define OFF_IDX   0
#define OFF_SC    32768
#define OFF_P     65536
#define OFF_IMP   1114112
#define OFF_LOAD  1114176

// ---------------- scratch ----------------
__device__ __nv_bfloat16 g_w1[(size_t)HDIM * DDIM];
__device__ __nv_bfloat16 g_wg_hi[(size_t)NEXP * DDIM];
__device__ __nv_bfloat16 g_wg_lo[(size_t)NEXP * DDIM];
__device__ float g_logits[(size_t)TOKENS * NEXP];
__device__ float g_diffpre[TOKENS];
__device__ float g_mu[TOKENS];
__device__ float g_rstd[TOKENS];
__device__ float g_imp[NEXP];
__device__ int   g_loadcnt[NEXP];

// =========================================================================
// prep: W1/Wg conversion + zero + LN stats. One launch.
// grid = 8192 (convert) + 2048 (stats, 8 tok/blk warp-per-token)
// =========================================================================
__global__ __launch_bounds__(256)
void prep_kernel(const float* __restrict__ W1, const float* __restrict__ Wg,
                 const float* __restrict__ x) {
    int b = blockIdx.x;
    int tid = threadIdx.x;
    if (b < 8192) {
        int i = b * 256 + tid;
        g_w1[i] = __float2bfloat16(W1[i]);
        if (i < NEXP * DDIM) {
            float v = Wg[i];
            __nv_bfloat16 hi = __float2bfloat16(v);
            g_wg_hi[i] = hi;
            g_wg_lo[i] = __float2bfloat16(v - __bfloat162float(hi));
        }
        if (i < TOKENS) g_diffpre[i] = 0.f;
        if (i < NEXP) { g_loadcnt[i] = 0; g_imp[i] = 0.f; }
    } else {
        int t = (b - 8192) * 8 + (tid >> 5);
        int lane = tid & 31;
        const float4* xr = (const float4*)(x + (size_t)t * DDIM);
        float s = 0.f, q = 0.f;
        #pragma unroll
        for (int k = 0; k < 16; k++) {
            float4 v = xr[lane + k * 32];
            s += v.x + v.y + v.z + v.w;
            q += v.x*v.x + v.y*v.y + v.z*v.z + v.w*v.w;
        }
        #pragma unroll
        for (int off = 16; off; off >>= 1) {
            s += __shfl_xor_sync(0xffffffffu, s, off);
            q += __shfl_xor_sync(0xffffffffu, q, off);
        }
        if (lane == 0) {
            float mean = s * (1.f / DDIM);
            float var  = q * (1.f / DDIM) - mean * mean;
            g_mu[t]   = mean;
            g_rstd[t] = rsqrtf(var + 1e-5f);
        }
    }
}

// =========================================================================
// logits_kernel: base-logits GEMM (bf16x3 split), double-buffered.
// One CTA = 128 tokens, 512 threads (16 warps, warp tile 16 x 32).
// =========================================================================
#define AST 40
#define LN_STG 15360   // bf16 elems per stage: Ah 5120 | Al 5120 | Wh 2560 | Wl 2560
#define LN_SMEM (2 * LN_STG * 2)

__global__ __launch_bounds__(512)
void logits_kernel(const float* __restrict__ x) {
    extern __shared__ __align__(16) __nv_bfloat16 SM[];

    int tile = blockIdx.x;
    int tid = threadIdx.x;
    int warp = tid >> 5, lane = tid & 31;
    const float* xb = x + (size_t)tile * 128 * DDIM;

    int lr = tid >> 2;          // 0..127 row
    int lc = (tid & 3) * 8;     // 0,8,16,24
    int wr = tid >> 2;          // 0..63 for W (tid<256)
    int wm = (warp & 7) * 16;
    int wn2 = (warp >> 3) * 32;

    float acc[4][4];
    #pragma unroll
    for (int j = 0; j < 4; j++)
        #pragma unroll
        for (int r = 0; r < 4; r++) acc[j][r] = 0.f;

    float4 v0 = *(const float4*)&xb[(size_t)lr * DDIM + lc];
    float4 v1 = *(const float4*)&xb[(size_t)lr * DDIM + lc + 4];
    uint4 wh, wl;
    if (tid < 256) {
        wh = *(const uint4*)&g_wg_hi[(size_t)wr * DDIM + lc];
        wl = *(const uint4*)&g_wg_lo[(size_t)wr * DDIM + lc];
    }

    // convert chunk 0 into stage 0
    {
        __nv_bfloat16* Ah = SM;
        __nv_bfloat16* Al = SM + 5120;
        __align__(16) __nv_bfloat16 hb[8], lb[8];
        float vv[8] = {v0.x, v0.y, v0.z, v0.w, v1.x, v1.y, v1.z, v1.w};
        #pragma unroll
        for (int i = 0; i < 8; i++) {
            __nv_bfloat16 b = __float2bfloat16(vv[i]);
            hb[i] = b;
            lb[i] = __float2bfloat16(vv[i] - __bfloat162float(b));
        }
        *(uint4*)&Ah[lr * AST + lc] = *(uint4*)hb;
        *(uint4*)&Al[lr * AST + lc] = *(uint4*)lb;
        if (tid < 256) {
            *(uint4*)&SM[10240 + wr * AST + lc] = wh;
            *(uint4*)&SM[12800 + wr * AST + lc] = wl;
        }
    }
    __syncthreads();

    #pragma unroll 2
    for (int kc = 0; kc < 64; kc++) {
        if (kc < 63) {
            int k0n = (kc + 1) * 32;
            v0 = *(const float4*)&xb[(size_t)lr * DDIM + k0n + lc];
            v1 = *(const float4*)&xb[(size_t)lr * DDIM + k0n + lc + 4];
            if (tid < 256) {
                wh = *(const uint4*)&g_wg_hi[(size_t)wr * DDIM + k0n + lc];
                wl = *(const uint4*)&g_wg_lo[(size_t)wr * DDIM + k0n + lc];
            }
        }

        {
            const __nv_bfloat16* Ahs = SM + (kc & 1) * LN_STG;
            const __nv_bfloat16* Als = Ahs + 5120;
            const __nv_bfloat16* Whs = Ahs + 10240;
            const __nv_bfloat16* Wls = Ahs + 12800;
            #pragma unroll
            for (int ks = 0; ks < 2; ks++) {
                int arow = wm + (lane >> 2);
                int colb = (lane & 3) * 2 + ks * 16;
                const __nv_bfloat16* pa  = &Ahs[arow * AST + colb];
                const __nv_bfloat16* pal = &Als[arow * AST + colb];
                uint32_t ah[4], al[4];
                ah[0] = *(const uint32_t*)(pa);
                ah[1] = *(const uint32_t*)(pa + 8 * AST);
                ah[2] = *(const uint32_t*)(pa + 8);
                ah[3] = *(const uint32_t*)(pa + 8 * AST + 8);
                al[0] = *(const uint32_t*)(pal);
                al[1] = *(const uint32_t*)(pal + 8 * AST);
                al[2] = *(const uint32_t*)(pal + 8);
                al[3] = *(const uint32_t*)(pal + 8 * AST + 8);
                #pragma unroll
                for (int j = 0; j < 4; j++) {
                    int brow = wn2 + j * 8 + (lane >> 2);
                    const __nv_bfloat16* pb  = &Whs[brow * AST + colb];
                    const __nv_bfloat16* pbl = &Wls[brow * AST + colb];
                    uint32_t bh0 = *(const uint32_t*)(pb);
                    uint32_t bh1 = *(const uint32_t*)(pb + 8);
                    uint32_t bl0 = *(const uint32_t*)(pbl);
                    uint32_t bl1 = *(const uint32_t*)(pbl + 8);
                    asm volatile(
                        "mma.sync.aligned.m16n8k16.row.col.f32.bf16.bf16.f32 "
                        "{%0,%1,%2,%3}, {%4,%5,%6,%7}, {%8,%9}, {%0,%1,%2,%3};\n"
                        : "+f"(acc[j][0]), "+f"(acc[j][1]), "+f"(acc[j][2]), "+f"(acc[j][3])
                        : "r"(ah[0]), "r"(ah[1]), "r"(ah[2]), "r"(ah[3]), "r"(bh0), "r"(bh1));
                    asm volatile(
                        "mma.sync.aligned.m16n8k16.row.col.f32.bf16.bf16.f32 "
                        "{%0,%1,%2,%3}, {%4,%5,%6,%7}, {%8,%9}, {%0,%1,%2,%3};\n"
                        : "+f"(acc[j][0]), "+f"(acc[j][1]), "+f"(acc[j][2]), "+f"(acc[j][3])
                        : "r"(ah[0]), "r"(ah[1]), "r"(ah[2]), "r"(ah[3]), "r"(bl0), "r"(bl1));
                    asm volatile(
                        "mma.sync.aligned.m16n8k16.row.col.f32.bf16.bf16.f32 "
                        "{%0,%1,%2,%3}, {%4,%5,%6,%7}, {%8,%9}, {%0,%1,%2,%3};\n"
                        : "+f"(acc[j][0]), "+f"(acc[j][1]), "+f"(acc[j][2]), "+f"(acc[j][3])
                        : "r"(al[0]), "r"(al[1]), "r"(al[2]), "r"(al[3]), "r"(bh0), "r"(bh1));
                }
            }
        }

        if (kc < 63) {
            __nv_bfloat16* Ahn = SM + ((kc + 1) & 1) * LN_STG;
            __nv_bfloat16* Aln = Ahn + 5120;
            __align__(16) __nv_bfloat16 hb[8], lb[8];
            float vv[8] = {v0.x, v0.y, v0.z, v0.w, v1.x, v1.y, v1.z, v1.w};
            #pragma unroll
            for (int i = 0; i < 8; i++) {
                __nv_bfloat16 b = __float2bfloat16(vv[i]);
                hb[i] = b;
                lb[i] = __float2bfloat16(vv[i] - __bfloat162float(b));
            }
            *(uint4*)&Ahn[lr * AST + lc] = *(uint4*)hb;
            *(uint4*)&Aln[lr * AST + lc] = *(uint4*)lb;
            if (tid < 256) {
                *(uint4*)&Ahn[10240 + wr * AST + lc] = wh;
                *(uint4*)&Ahn[12800 + wr * AST + lc] = wl;
            }
        }
        __syncthreads();
    }

    #pragma unroll
    for (int j = 0; j < 4; j++) {
        int row = tile * 128 + wm + (lane >> 2);
        int col = wn2 + j * 8 + (lane & 3) * 2;
        float2 c01; c01.x = acc[j][0]; c01.y = acc[j][1];
        float2 c23; c23.x = acc[j][2]; c23.y = acc[j][3];
        *(float2*)&g_logits[(size_t)row * NEXP + col] = c01;
        *(float2*)&g_logits[(size_t)(row + 8) * NEXP + col] = c23;
    }
}

// =========================================================================
// gemm1: BM=128 x BN=256 x BK=32, bf16 MMA fp32 accum,
// LN applied in-kernel from x fp32 (mu/rstd from prep), 3-stage B-ring.
// =========================================================================
#define G2_STAGES 3
#define G2_BK     32
#define G2_BN     256
#define G2_BBYTES 16384
#define G2_ABYTES 8192
#define G2_A_OFF  (G2_STAGES * G2_BBYTES)
#define G2_GB_OFF (G2_A_OFF + 2 * G2_ABYTES)
#define G2_SMEM   (G2_GB_OFF + 16384)
#define G2_CHUNKS (DDIM / G2_BK)

__device__ __forceinline__ uint32_t smem_u32(const void* p) {
    uint32_t a;
    asm("{ .reg .u64 t; cvta.to.shared.u64 t, %1; cvt.u32.u64 %0, t; }" : "=r"(a) : "l"(p));
    return a;
}
__device__ __forceinline__ uint32_t g1_sw(uint32_t r, uint32_t c) {
    return r * 64 + ((c ^ ((r >> 1) & 3)) * 16);
}
__device__ __forceinline__ void ldsm_x4(uint32_t& r0, uint32_t& r1, uint32_t& r2, uint32_t& r3,
                                        uint32_t addr) {
    asm volatile("ldmatrix.sync.aligned.m8n8.x4.shared.b16 {%0,%1,%2,%3}, [%4];"
                 : "=r"(r0), "=r"(r1), "=r"(r2), "=r"(r3) : "r"(addr));
}
__device__ __forceinline__ float gelu_exact(float v) {
    return 0.5f * v * (1.0f + erff(v * 0.70710678118654752440f));
}

__device__ __forceinline__ void g2_stage_B(uint32_t sB, const __nv_bfloat16* Bg,
                                           int k0, int tid) {
    #pragma unroll
    for (int i = 0; i < 4; i++) {
        int idx = tid + i * 256;
        int r = idx >> 2, c = idx & 3;
        uint32_t dst = sB + g1_sw(r, c);
        asm volatile("cp.async.cg.shared.global [%0], [%1], 16;\n"
                     :: "r"(dst), "l"(Bg + (size_t)r * DDIM + k0 + c * 8));
    }
    asm volatile("cp.async.commit_group;\n");
}

__global__ __launch_bounds__(256, 1)
void gemm1_mma(const float* __restrict__ x, const float* __restrict__ gamma,
               const float* __restrict__ beta, const float* __restrict__ W2) {
    extern __shared__ __align__(128) char g1sm[];
    uint32_t sb = smem_u32(g1sm);
    int tid = threadIdx.x;
    int warp = tid >> 5, lane = tid & 31;
    int bn = blockIdx.x, bm = blockIdx.y;
    int wm = (warp & 1) * 64;
    int wn = (warp >> 1) * 64;

    const float* xb = x + (size_t)(bm * 128) * DDIM;
    const __nv_bfloat16* Bg = g_w1 + (size_t)(bn * G2_BN) * DDIM;

    float* sGB = (float*)(g1sm + G2_GB_OFF);
    #pragma unroll
    for (int i = 0; i < 2; i++) {
        int idx = tid + i * 256;
        ((float4*)sGB)[idx]       = ((const float4*)gamma)[idx];
        ((float4*)sGB)[idx + 512] = ((const float4*)beta)[idx];
    }

    int r0 = tid >> 1;
    int hsel = tid & 1;
    float mu = g_mu[bm * 128 + r0];
    float rs = g_rstd[bm * 128 + r0];

    float acc[4][8][4];
    #pragma unroll
    for (int i = 0; i < 4; i++)
        #pragma unroll
        for (int j = 0; j < 8; j++)
            #pragma unroll
            for (int r = 0; r < 4; r++) acc[i][j][r] = 0.f;

    g2_stage_B(sb + 0 * G2_BBYTES, Bg, 0, tid);
    g2_stage_B(sb + 1 * G2_BBYTES, Bg, G2_BK, tid);
    float4 xv[4];
    #pragma unroll
    for (int i = 0; i < 4; i++)
        xv[i] = *(const float4*)&xb[(size_t)r0 * DDIM + hsel * 16 + i * 4];

    __syncthreads();

    int lrow = lane & 15;
    int lsel = lane >> 4;

    #pragma unroll 1
    for (int c = 0; c < G2_CHUNKS; c++) {
        if (c + 2 < G2_CHUNKS)
            g2_stage_B(sb + ((c + 2) % G2_STAGES) * G2_BBYTES, Bg, (c + 2) * G2_BK, tid);

        {
            const float* gg = sGB + c * 32 + hsel * 16;
            const float* bb = gg + 2048;
            uint32_t sA = sb + G2_A_OFF + (c & 1) * G2_ABYTES;
            __align__(16) __nv_bfloat16 ob[16];
            #pragma unroll
            for (int i = 0; i < 4; i++) {
                float4 t4 = xv[i];
                float4 g4 = *(const float4*)(gg + i * 4);
                float4 b4 = *(const float4*)(bb + i * 4);
                ob[i*4+0] = __float2bfloat16((t4.x - mu) * rs * g4.x + b4.x);
                ob[i*4+1] = __float2bfloat16((t4.y - mu) * rs * g4.y + b4.y);
                ob[i*4+2] = __float2bfloat16((t4.z - mu) * rs * g4.z + b4.z);
                ob[i*4+3] = __float2bfloat16((t4.w - mu) * rs * g4.w + b4.w);
            }
            #pragma unroll
            for (int j = 0; j < 2; j++) {
                uint32_t dst = sA + g1_sw((uint32_t)r0, (uint32_t)(hsel * 2 + j));
                *(uint4*)(g1sm + (dst - sb)) = *(uint4*)&ob[j * 8];
            }
        }

        if (c + 1 < G2_CHUNKS) {
            #pragma unroll
            for (int i = 0; i < 4; i++)
                xv[i] = *(const float4*)&xb[(size_t)r0 * DDIM + (c + 1) * G2_BK + hsel * 16 + i * 4];
        }

        if (c + 2 < G2_CHUNKS) {
            asm volatile("cp.async.wait_group 2;\n");
        } else if (c + 2 == G2_CHUNKS) {
            asm volatile("cp.async.wait_group 1;\n");
        } else {
            asm volatile("cp.async.wait_group 0;\n");
        }
        __syncthreads();

        uint32_t sA = sb + G2_A_OFF + (c & 1) * G2_ABYTES;
        uint32_t sB = sb + (c % G2_STAGES) * G2_BBYTES;

        #pragma unroll
        for (int ks = 0; ks < 2; ks++) {
            uint32_t af[4][4], bf[8][2];
            #pragma unroll
            for (int i = 0; i < 4; i++) {
                uint32_t r = (uint32_t)(wm + i * 16 + lrow);
                ldsm_x4(af[i][0], af[i][1], af[i][2], af[i][3],
                        sA + g1_sw(r, (uint32_t)(ks * 2 + lsel)));
            }
            #pragma unroll
            for (int jb = 0; jb < 4; jb++) {
                uint32_t r = (uint32_t)(wn + jb * 16 + lrow);
                uint32_t q0, q1, q2, q3;
                ldsm_x4(q0, q1, q2, q3, sB + g1_sw(r, (uint32_t)(ks * 2 + lsel)));
                bf[jb * 2][0] = q0;     bf[jb * 2][1] = q2;
                bf[jb * 2 + 1][0] = q1; bf[jb * 2 + 1][1] = q3;
            }
            #pragma unroll
            for (int i = 0; i < 4; i++)
                #pragma unroll
                for (int j = 0; j < 8; j++) {
                    asm volatile(
                        "mma.sync.aligned.m16n8k16.row.col.f32.bf16.bf16.f32 "
                        "{%0,%1,%2,%3}, {%4,%5,%6,%7}, {%8,%9}, {%0,%1,%2,%3};\n"
                        : "+f"(acc[i][j][0]), "+f"(acc[i][j][1]),
                          "+f"(acc[i][j][2]), "+f"(acc[i][j][3])
                        : "r"(af[i][0]), "r"(af[i][1]), "r"(af[i][2]), "r"(af[i][3]),
                          "r"(bf[j][0]), "r"(bf[j][1]));
                }
        }
        __syncthreads();
    }

    float part0[4] = {0.f, 0.f, 0.f, 0.f};
    float part1[4] = {0.f, 0.f, 0.f, 0.f};
    #pragma unroll
    for (int j = 0; j < 8; j++) {
        int n = bn * G2_BN + wn + j * 8 + (lane & 3) * 2;
        float w20 = W2[n], w21 = W2[n + 1];
        #pragma unroll
        for (int i = 0; i < 4; i++) {
            part0[i] += gelu_exact(acc[i][j][0]) * w20 + gelu_exact(acc[i][j][1]) * w21;
            part1[i] += gelu_exact(acc[i][j][2]) * w20 + gelu_exact(acc[i][j][3]) * w21;
        }
    }
    #pragma unroll
    for (int i = 0; i < 4; i++) {
        part0[i] += __shfl_xor_sync(0xffffffffu, part0[i], 1);
        part0[i] += __shfl_xor_sync(0xffffffffu, part0[i], 2);
        part1[i] += __shfl_xor_sync(0xffffffffu, part1[i], 1);
        part1[i] += __shfl_xor_sync(0xffffffffu, part1[i], 2);
    }
    if ((lane & 3) == 0) {
        int mbase = bm * 128 + wm + (lane >> 2);
        #pragma unroll
        for (int i = 0; i < 4; i++) {
            atomicAdd(&g_diffpre[mbase + i * 16], part0[i]);
            atomicAdd(&g_diffpre[mbase + i * 16 + 8], part1[i]);
        }
    }
}

// ---------------- finalize: 4 tokens/warp, fast exp, recip denom ----------------
__global__ __launch_bounds__(256)
void finalize_kernel(float* __restrict__ out) {
    __shared__ float simp[8 * 64];
    int warp = threadIdx.x >> 5;
    int lane = threadIdx.x & 31;
    int tbase = blockIdx.x * 32 + warp * 4;

    float2 lg[4]; float dp[4];
    #pragma unroll
    for (int tt = 0; tt < 4; tt++) {
        lg[tt] = *(const float2*)&g_logits[(size_t)(tbase + tt) * NEXP + lane * 2];
        dp[tt] = g_diffpre[tbase + tt];
    }

    float pimp0 = 0.f, pimp1 = 0.f;
    #pragma unroll
    for (int tt = 0; tt < 4; tt++) {
        int t = tbase + tt;
        float diff = 1.f / (1.f + __expf(-dp[tt]));
        float rden = 1.f / (1.f + diff);
        float l0 = lg[tt].x * rden;
        float l1 = lg[tt].y * rden;

        float e0 = __expf(l0), e1 = __expf(l1);
        float sum = e0 + e1;
        #pragma unroll
        for (int off = 16; off; off >>= 1) sum += __shfl_xor_sync(0xffffffffu, sum, off);
        float inv = 1.f / sum;
        float p0 = e0 * inv, p1 = e1 * inv;
        *(float2*)&out[OFF_P + (size_t)t * NEXP + lane * 2] = make_float2(p0, p1);
        pimp0 += p0; pimp1 += p1;

        float bv; int bi;
        if (l1 > l0) { bv = l1; bi = lane * 2 + 1; } else { bv = l0; bi = lane * 2; }
        #pragma unroll
        for (int off = 16; off; off >>= 1) {
            float ov = __shfl_xor_sync(0xffffffffu, bv, off);
            int   oi = __shfl_xor_sync(0xffffffffu, bi, off);
            if (ov > bv || (ov == bv && oi < bi)) { bv = ov; bi = oi; }
        }
        int top1 = bi;
        float c0 = (lane * 2     == top1) ? -INFINITY : l0;
        float c1 = (lane * 2 + 1 == top1) ? -INFINITY : l1;
        float bv2; int bi2;
        if (c1 > c0) { bv2 = c1; bi2 = lane * 2 + 1; } else { bv2 = c0; bi2 = lane * 2; }
        #pragma unroll
        for (int off = 16; off; off >>= 1) {
            float ov = __shfl_xor_sync(0xffffffffu, bv2, off);
            int   oi = __shfl_xor_sync(0xffffffffu, bi2, off);
            if (ov > bv2 || (ov == bv2 && oi < bi2)) { bv2 = ov; bi2 = oi; }
        }
        int top2 = bi2;

        float sel1 = (top1 & 1) ? p1 : p0;
        float pt1 = __shfl_sync(0xffffffffu, sel1, top1 >> 1);
        float sel2 = (top2 & 1) ? p1 : p0;
        float pt2 = __shfl_sync(0xffffffffu, sel2, top2 >> 1);

        float s1 = (1.0f - pt1) + pt1;
        float s2 = (1.0f - pt2) + pt2;
        float dsum = fmaxf(s1 + s2, 1e-9f);

        if (lane == 0) {
            out[OFF_IDX + t * 2]     = (float)top1;
            out[OFF_IDX + t * 2 + 1] = (float)top2;
            out[OFF_SC + t * 2]      = s1 / dsum;
            out[OFF_SC + t * 2 + 1]  = s2 / dsum;
            atomicAdd(&g_loadcnt[top1], 1);
            atomicAdd(&g_loadcnt[top2], 1);
        }
    }

    simp[warp * 64 + lane * 2]     = pimp0;
    simp[warp * 64 + lane * 2 + 1] = pimp1;
    __syncthreads();
    if (threadIdx.x < 64) {
        float a = 0.f;
        #pragma unroll
        for (int w = 0; w < 8; w++) a += simp[w * 64 + threadIdx.x];
        atomicAdd(&g_imp[threadIdx.x], a);
    }
}

// ---------------- write importance / load ----------------
__global__ void stats_out_kernel(float* __restrict__ out) {
    int e = threadIdx.x;
    out[OFF_IMP + e]  = g_imp[e] * (1.f / TOKENS);
    out[OFF_LOAD + e] = (float)g_loadcnt[e] * (1.f / TOKENS);
}

// ---------------- launch: fork logits || gemm1 via events ----------------
extern "C" void kernel_launch(void* const* d_in, const int* in_sizes, int n_in,
                              void* d_out, int out_size) {
    const float* x     = (const float*)d_in[0];
    const float* Wg    = (const float*)d_in[1];
    const float* gamma = (const float*)d_in[2];
    const float* beta  = (const float*)d_in[3];
    const float* W1    = (const float*)d_in[4];
    const float* W2    = (const float*)d_in[5];
    float* out = (float*)d_out;

    static cudaStream_t s2 = nullptr;
    static cudaEvent_t ev_fork = nullptr, ev_join = nullptr;
    static bool init_done = false;
    if (!init_done) {
        cudaStreamCreateWithFlags(&s2, cudaStreamNonBlocking);
        cudaEventCreateWithFlags(&ev_fork, cudaEventDisableTiming);
        cudaEventCreateWithFlags(&ev_join, cudaEventDisableTiming);
        cudaFuncSetAttribute(gemm1_mma, cudaFuncAttributeMaxDynamicSharedMemorySize, G2_SMEM);
        cudaFuncSetAttribute(logits_kernel, cudaFuncAttributeMaxDynamicSharedMemorySize, LN_SMEM);
        init_done = true;
    }

    prep_kernel<<<10240, 256>>>(W1, Wg, x);

    // fork: logits on s2, gemm1 stays on the capture (default) stream
    cudaEventRecord(ev_fork, 0);
    cudaStreamWaitEvent(s2, ev_fork, 0);
    logits_kernel<<<TOKENS / 128, 512, LN_SMEM, s2>>>(x);
    cudaEventRecord(ev_join, s2);

    dim3 g3(HDIM / G2_BN, TOKENS / 128);
    gemm1_mma<<<g3, 256, G2_SMEM>>>(x, gamma, beta, W2);

    // join before finalize
    cudaStreamWaitEvent(0, ev_join, 0);
    finalize_kernel<<<TOKENS / 32, 256>>>(out);
    stats_out_kernel<<<1, NEXP>>>(out);
}

// round 12
// speedup vs baseline: 1.0059x; 1.0059x over previous
#include <cuda_runtime.h>
#include <cuda_bf16.h>
#include <math.h>
#include <stdint.h>

#define TOKENS 16384
#define DDIM   2048
#define NEXP   64
#define HDIM   1024

// Output layout (float32): idx [16384*2] | scores [16384*2] | probs [16384*64] | imp [64] | load [64]
#define OFF_IDX   0
#define OFF_SC    32768
#define OFF_P     65536
#define OFF_IMP   1114112
#define OFF_LOAD  1114176

// ---------------- scratch ----------------
__device__ __nv_bfloat16 g_w1[(size_t)HDIM * DDIM];        // W1 * gamma, bf16
__device__ __nv_bfloat16 g_wg_hi[(size_t)NEXP * DDIM];
__device__ __nv_bfloat16 g_wg_lo[(size_t)NEXP * DDIM];
__device__ float g_lpart[(size_t)4 * TOKENS * NEXP];       // logits partials per K-quarter
__device__ float g_diffpre[TOKENS];
__device__ float g_mu[TOKENS];
__device__ float g_rstd[TOKENS];
__device__ float g_c1[HDIM];
__device__ float g_c2[HDIM];
__device__ float g_imp[NEXP];
__device__ int   g_loadcnt[NEXP];

// =========================================================================
// prep: W1*gamma -> bf16, Wg hi/lo, zeros, LN stats, C1/C2. One launch.
// grid = 8192 (convert) + 2048 (stats) + 128 (C1/C2)
// =========================================================================
__global__ __launch_bounds__(256)
void prep_kernel(const float* __restrict__ W1, const float* __restrict__ Wg,
                 const float* __restrict__ x, const float* __restrict__ gamma,
                 const float* __restrict__ beta) {
    int b = blockIdx.x;
    int tid = threadIdx.x;
    if (b < 8192) {
        int i = b * 256 + tid;
        g_w1[i] = __float2bfloat16(W1[i] * gamma[i & (DDIM - 1)]);
        if (i < NEXP * DDIM) {
            float v = Wg[i];
            __nv_bfloat16 hi = __float2bfloat16(v);
            g_wg_hi[i] = hi;
            g_wg_lo[i] = __float2bfloat16(v - __bfloat162float(hi));
        }
        if (i < TOKENS) g_diffpre[i] = 0.f;
        if (i < NEXP) { g_loadcnt[i] = 0; g_imp[i] = 0.f; }
    } else if (b < 10240) {
        int t = (b - 8192) * 8 + (tid >> 5);
        int lane = tid & 31;
        const float4* xr = (const float4*)(x + (size_t)t * DDIM);
        float s = 0.f, q = 0.f;
        #pragma unroll
        for (int k = 0; k < 16; k++) {
            float4 v = xr[lane + k * 32];
            s += v.x + v.y + v.z + v.w;
            q += v.x*v.x + v.y*v.y + v.z*v.z + v.w*v.w;
        }
        #pragma unroll
        for (int off = 16; off; off >>= 1) {
            s += __shfl_xor_sync(0xffffffffu, s, off);
            q += __shfl_xor_sync(0xffffffffu, q, off);
        }
        if (lane == 0) {
            float mean = s * (1.f / DDIM);
            float var  = q * (1.f / DDIM) - mean * mean;
            g_mu[t]   = mean;
            g_rstd[t] = rsqrtf(var + 1e-5f);
        }
    } else {
        int n = (b - 10240) * 8 + (tid >> 5);
        int lane = tid & 31;
        const float* wr = W1 + (size_t)n * DDIM;
        float c1 = 0.f, c2 = 0.f;
        #pragma unroll 8
        for (int k = 0; k < 64; k++) {
            int d = lane + k * 32;
            float w = wr[d];
            c1 += w * gamma[d];
            c2 += w * beta[d];
        }
        #pragma unroll
        for (int off = 16; off; off >>= 1) {
            c1 += __shfl_xor_sync(0xffffffffu, c1, off);
            c2 += __shfl_xor_sync(0xffffffffu, c2, off);
        }
        if (lane == 0) { g_c1[n] = c1; g_c2[n] = c2; }
    }
}

// =========================================================================
// fused gemm: grid (4, 128). Each CTA: W1 GEMM (BM=128 x BN=256, all K)
// + logits GEMM (M=128 x N=64, K-quarter [bn*512,(bn+1)*512), bf16x3 split).
// A = bf16(x) raw, shared by both paths. W1 has gamma folded in;
// LN affine applied in epilogue via rs, mu, C1, C2.
// =========================================================================
#define G2_STAGES 3
#define G2_BK     32
#define G2_BN     256
#define G2_BBYTES 16384
#define G2_ABYTES 8192
#define G2_A_OFF   (G2_STAGES * G2_BBYTES)     // 49152: A_hi 2 x 8KB
#define G2_ALO_OFF (G2_A_OFF + 16384)          // 65536: A_lo 2 x 8KB
#define G2_WG_OFF  (G2_ALO_OFF + 16384)        // 81920: Wg ring 3 x 8KB (hi|lo)
#define G2_SMEM    (G2_WG_OFF + 24576)         // 106496
#define G2_CHUNKS  (DDIM / G2_BK)

__device__ __forceinline__ uint32_t smem_u32(const void* p) {
    uint32_t a;
    asm("{ .reg .u64 t; cvta.to.shared.u64 t, %1; cvt.u32.u64 %0, t; }" : "=r"(a) : "l"(p));
    return a;
}
__device__ __forceinline__ uint32_t g1_sw(uint32_t r, uint32_t c) {
    return r * 64 + ((c ^ ((r >> 1) & 3)) * 16);
}
__device__ __forceinline__ void ldsm_x4(uint32_t& r0, uint32_t& r1, uint32_t& r2, uint32_t& r3,
                                        uint32_t addr) {
    asm volatile("ldmatrix.sync.aligned.m8n8.x4.shared.b16 {%0,%1,%2,%3}, [%4];"
                 : "=r"(r0), "=r"(r1), "=r"(r2), "=r"(r3) : "r"(addr));
}
__device__ __forceinline__ float gelu_exact(float v) {
    return 0.5f * v * (1.0f + erff(v * 0.70710678118654752440f));
}
#define MMA_BF16(acc, a, b0, b1) \
    asm volatile( \
        "mma.sync.aligned.m16n8k16.row.col.f32.bf16.bf16.f32 " \
        "{%0,%1,%2,%3}, {%4,%5,%6,%7}, {%8,%9}, {%0,%1,%2,%3};\n" \
        : "+f"((acc)[0]), "+f"((acc)[1]), "+f"((acc)[2]), "+f"((acc)[3]) \
        : "r"((a)[0]), "r"((a)[1]), "r"((a)[2]), "r"((a)[3]), "r"(b0), "r"(b1))

__global__ __launch_bounds__(256, 1)
void gemm_fused(const float* __restrict__ x, const float* __restrict__ W2) {
    extern __shared__ __align__(128) char g1sm[];
    uint32_t sb = smem_u32(g1sm);
    int tid = threadIdx.x;
    int warp = tid >> 5, lane = tid & 31;
    int bn = blockIdx.x, bm = blockIdx.y;
    int wm = (warp & 1) * 64;
    int wn = (warp >> 1) * 64;
    int qlo = bn * 16, qhi = qlo + 16;     // chunk quarter for logits

    const float* xb = x + (size_t)(bm * 128) * DDIM;
    const __nv_bfloat16* Bg = g_w1 + (size_t)(bn * G2_BN) * DDIM;

    int r0 = tid >> 1;
    int hsel = tid & 1;
    int lrow = lane & 15;
    int lsel = lane >> 4;

    float acc[4][8][4];
    #pragma unroll
    for (int i = 0; i < 4; i++)
        #pragma unroll
        for (int j = 0; j < 8; j++)
            #pragma unroll
            for (int r = 0; r < 4; r++) acc[i][j][r] = 0.f;
    float lacc[8][4];
    #pragma unroll
    for (int j = 0; j < 8; j++)
        #pragma unroll
        for (int r = 0; r < 4; r++) lacc[j][r] = 0.f;

    // stage chunk cn: B always; Wg (hi+lo) if cn in quarter. One commit group.
    auto stage_chunk = [&](int cn) {
        uint32_t bbase = sb + (cn % G2_STAGES) * G2_BBYTES;
        #pragma unroll
        for (int i = 0; i < 4; i++) {
            int idx = tid + i * 256;
            int r = idx >> 2, c = idx & 3;
            uint32_t dst = bbase + g1_sw(r, c);
            asm volatile("cp.async.cg.shared.global [%0], [%1], 16;\n"
                         :: "r"(dst), "l"(Bg + (size_t)r * DDIM + cn * G2_BK + c * 8));
        }
        if (cn >= qlo && cn < qhi) {
            uint32_t wbase = sb + G2_WG_OFF + ((cn - qlo) % 3) * 8192;
            int r = tid >> 2, c = tid & 3;
            uint32_t o = g1_sw(r, c);
            asm volatile("cp.async.cg.shared.global [%0], [%1], 16;\n"
                         :: "r"(wbase + o),
                            "l"(g_wg_hi + (size_t)r * DDIM + cn * G2_BK + c * 8));
            asm volatile("cp.async.cg.shared.global [%0], [%1], 16;\n"
                         :: "r"(wbase + 4096 + o),
                            "l"(g_wg_lo + (size_t)r * DDIM + cn * G2_BK + c * 8));
        }
        asm volatile("cp.async.commit_group;\n");
    };

    stage_chunk(0);
    stage_chunk(1);
    float4 xv[4];
    #pragma unroll
    for (int i = 0; i < 4; i++)
        xv[i] = *(const float4*)&xb[(size_t)r0 * DDIM + hsel * 16 + i * 4];

    #pragma unroll 1
    for (int c = 0; c < G2_CHUNKS; c++) {
        bool inq = (c >= qlo) & (c < qhi);
        if (c + 2 < G2_CHUNKS) stage_chunk(c + 2);

        // convert x chunk c -> A_hi (+ A_lo when in quarter)
        {
            uint32_t sA   = sb + G2_A_OFF + (c & 1) * G2_ABYTES;
            uint32_t sAlo = sb + G2_ALO_OFF + (c & 1) * G2_ABYTES;
            __align__(16) __nv_bfloat16 hb[16], lb[16];
            float vv[16] = {xv[0].x, xv[0].y, xv[0].z, xv[0].w,
                            xv[1].x, xv[1].y, xv[1].z, xv[1].w,
                            xv[2].x, xv[2].y, xv[2].z, xv[2].w,
                            xv[3].x, xv[3].y, xv[3].z, xv[3].w};
            #pragma unroll
            for (int e = 0; e < 16; e++) {
                __nv_bfloat16 h = __float2bfloat16(vv[e]);
                hb[e] = h;
                lb[e] = __float2bfloat16(vv[e] - __bfloat162float(h));
            }
            #pragma unroll
            for (int j = 0; j < 2; j++) {
                uint32_t o = g1_sw((uint32_t)r0, (uint32_t)(hsel * 2 + j));
                *(uint4*)(g1sm + (sA + o - sb)) = *(uint4*)&hb[j * 8];
                if (inq)
                    *(uint4*)(g1sm + (sAlo + o - sb)) = *(uint4*)&lb[j * 8];
            }
        }

        if (c + 1 < G2_CHUNKS) {
            #pragma unroll
            for (int i = 0; i < 4; i++)
                xv[i] = *(const float4*)&xb[(size_t)r0 * DDIM + (c + 1) * G2_BK + hsel * 16 + i * 4];
        }

        if (c + 2 < G2_CHUNKS) {
            asm volatile("cp.async.wait_group 2;\n");
        } else if (c + 2 == G2_CHUNKS) {
            asm volatile("cp.async.wait_group 1;\n");
        } else {
            asm volatile("cp.async.wait_group 0;\n");
        }
        __syncthreads();

        uint32_t sA   = sb + G2_A_OFF + (c & 1) * G2_ABYTES;
        uint32_t sAlo = sb + G2_ALO_OFF + (c & 1) * G2_ABYTES;
        uint32_t sB   = sb + (c % G2_STAGES) * G2_BBYTES;
        uint32_t sWg  = sb + G2_WG_OFF + ((c - qlo) % 3) * 8192;

        #pragma unroll
        for (int ks = 0; ks < 2; ks++) {
            uint32_t af[4][4], bf[8][2];
            #pragma unroll
            for (int i = 0; i < 4; i++) {
                uint32_t r = (uint32_t)(wm + i * 16 + lrow);
                ldsm_x4(af[i][0], af[i][1], af[i][2], af[i][3],
                        sA + g1_sw(r, (uint32_t)(ks * 2 + lsel)));
            }
            #pragma unroll
            for (int jb = 0; jb < 4; jb++) {
                uint32_t r = (uint32_t)(wn + jb * 16 + lrow);
                uint32_t q0, q1, q2, q3;
                ldsm_x4(q0, q1, q2, q3, sB + g1_sw(r, (uint32_t)(ks * 2 + lsel)));
                bf[jb * 2][0] = q0;     bf[jb * 2][1] = q2;
                bf[jb * 2 + 1][0] = q1; bf[jb * 2 + 1][1] = q3;
            }
            #pragma unroll
            for (int i = 0; i < 4; i++)
                #pragma unroll
                for (int j = 0; j < 8; j++)
                    MMA_BF16(acc[i][j], af[i], bf[j][0], bf[j][1]);

            if (inq) {
                uint32_t aoff = g1_sw((uint32_t)(warp * 16 + lrow),
                                      (uint32_t)(ks * 2 + lsel));
                uint32_t ahq[4], alq[4];
                ldsm_x4(ahq[0], ahq[1], ahq[2], ahq[3], sA + aoff);
                ldsm_x4(alq[0], alq[1], alq[2], alq[3], sAlo + aoff);
                uint32_t wgh[8][2], wgl[8][2];
                #pragma unroll
                for (int jb = 0; jb < 4; jb++) {
                    uint32_t o = g1_sw((uint32_t)(jb * 16 + lrow),
                                       (uint32_t)(ks * 2 + lsel));
                    uint32_t q0, q1, q2, q3;
                    ldsm_x4(q0, q1, q2, q3, sWg + o);
                    wgh[jb * 2][0] = q0;     wgh[jb * 2][1] = q2;
                    wgh[jb * 2 + 1][0] = q1; wgh[jb * 2 + 1][1] = q3;
                    ldsm_x4(q0, q1, q2, q3, sWg + 4096 + o);
                    wgl[jb * 2][0] = q0;     wgl[jb * 2][1] = q2;
                    wgl[jb * 2 + 1][0] = q1; wgl[jb * 2 + 1][1] = q3;
                }
                #pragma unroll
                for (int j = 0; j < 8; j++) {
                    MMA_BF16(lacc[j], ahq, wgh[j][0], wgh[j][1]);
                    MMA_BF16(lacc[j], ahq, wgl[j][0], wgl[j][1]);
                    MMA_BF16(lacc[j], alq, wgh[j][0], wgh[j][1]);
                }
            }
        }
        __syncthreads();
    }

    // ---- logits partials: warp covers rows [warp*16, warp*16+16), all 64 experts ----
    {
        float* lp = g_lpart + (size_t)bn * TOKENS * NEXP;
        int rowa = bm * 128 + warp * 16 + (lane >> 2);
        #pragma unroll
        for (int j = 0; j < 8; j++) {
            int col = j * 8 + (lane & 3) * 2;
            float2 c01; c01.x = lacc[j][0]; c01.y = lacc[j][1];
            float2 c23; c23.x = lacc[j][2]; c23.y = lacc[j][3];
            *(float2*)&lp[(size_t)rowa * NEXP + col] = c01;
            *(float2*)&lp[(size_t)(rowa + 8) * NEXP + col] = c23;
        }
    }

    // ---- W1 epilogue: h1 = rs*acc - rs*mu*C1 + C2; gelu*W2; reduce ----
    float part0[4] = {0.f, 0.f, 0.f, 0.f};
    float part1[4] = {0.f, 0.f, 0.f, 0.f};
    float rs0[4], rm0[4], rs1[4], rm1[4];
    #pragma unroll
    for (int i = 0; i < 4; i++) {
        int m0 = bm * 128 + wm + i * 16 + (lane >> 2);
        rs0[i] = g_rstd[m0];     rm0[i] = rs0[i] * g_mu[m0];
        rs1[i] = g_rstd[m0 + 8]; rm1[i] = rs1[i] * g_mu[m0 + 8];
    }
    #pragma unroll
    for (int j = 0; j < 8; j++) {
        int n = bn * G2_BN + wn + j * 8 + (lane & 3) * 2;
        float2 c1 = *(const float2*)&g_c1[n];
        float2 c2 = *(const float2*)&g_c2[n];
        float2 w2 = *(const float2*)&W2[n];
        #pragma unroll
        for (int i = 0; i < 4; i++) {
            float h00 = rs0[i] * acc[i][j][0] - rm0[i] * c1.x + c2.x;
            float h01 = rs0[i] * acc[i][j][1] - rm0[i] * c1.y + c2.y;
            float h10 = rs1[i] * acc[i][j][2] - rm1[i] * c1.x + c2.x;
            float h11 = rs1[i] * acc[i][j][3] - rm1[i] * c1.y + c2.y;
            part0[i] += gelu_exact(h00) * w2.x + gelu_exact(h01) * w2.y;
            part1[i] += gelu_exact(h10) * w2.x + gelu_exact(h11) * w2.y;
        }
    }
    #pragma unroll
    for (int i = 0; i < 4; i++) {
        part0[i] += __shfl_xor_sync(0xffffffffu, part0[i], 1);
        part0[i] += __shfl_xor_sync(0xffffffffu, part0[i], 2);
        part1[i] += __shfl_xor_sync(0xffffffffu, part1[i], 1);
        part1[i] += __shfl_xor_sync(0xffffffffu, part1[i], 2);
    }
    if ((lane & 3) == 0) {
        int mbase = bm * 128 + wm + (lane >> 2);
        #pragma unroll
        for (int i = 0; i < 4; i++) {
            atomicAdd(&g_diffpre[mbase + i * 16], part0[i]);
            atomicAdd(&g_diffpre[mbase + i * 16 + 8], part1[i]);
        }
    }
}

// ---------------- finalize: sum logits partials, softmax/top-2, importance ----------------
__global__ __launch_bounds__(256)
void finalize_kernel(float* __restrict__ out) {
    __shared__ float simp[8 * 64];
    int warp = threadIdx.x >> 5;
    int lane = threadIdx.x & 31;
    int tbase = blockIdx.x * 32 + warp * 4;

    float2 lg[4]; float dp[4];
    #pragma unroll
    for (int tt = 0; tt < 4; tt++) {
        size_t o = (size_t)(tbase + tt) * NEXP + lane * 2;
        float2 a0 = *(const float2*)&g_lpart[o];
        float2 a1 = *(const float2*)&g_lpart[(size_t)TOKENS * NEXP + o];
        float2 a2 = *(const float2*)&g_lpart[(size_t)2 * TOKENS * NEXP + o];
        float2 a3 = *(const float2*)&g_lpart[(size_t)3 * TOKENS * NEXP + o];
        lg[tt].x = (a0.x + a1.x) + (a2.x + a3.x);
        lg[tt].y = (a0.y + a1.y) + (a2.y + a3.y);
        dp[tt] = g_diffpre[tbase + tt];
    }

    float pimp0 = 0.f, pimp1 = 0.f;
    #pragma unroll
    for (int tt = 0; tt < 4; tt++) {
        int t = tbase + tt;
        float diff = 1.f / (1.f + __expf(-dp[tt]));
        float rden = 1.f / (1.f + diff);
        float l0 = lg[tt].x * rden;
        float l1 = lg[tt].y * rden;

        float e0 = __expf(l0), e1 = __expf(l1);
        float sum = e0 + e1;
        #pragma unroll
        for (int off = 16; off; off >>= 1) sum += __shfl_xor_sync(0xffffffffu, sum, off);
        float inv = 1.f / sum;
        float p0 = e0 * inv, p1 = e1 * inv;
        *(float2*)&out[OFF_P + (size_t)t * NEXP + lane * 2] = make_float2(p0, p1);
        pimp0 += p0; pimp1 += p1;

        float bv; int bi;
        if (l1 > l0) { bv = l1; bi = lane * 2 + 1; } else { bv = l0; bi = lane * 2; }
        #pragma unroll
        for (int off = 16; off; off >>= 1) {
            float ov = __shfl_xor_sync(0xffffffffu, bv, off);
            int   oi = __shfl_xor_sync(0xffffffffu, bi, off);
            if (ov > bv || (ov == bv && oi < bi)) { bv = ov; bi = oi; }
        }
        int top1 = bi;
        float c0 = (lane * 2     == top1) ? -INFINITY : l0;
        float c1 = (lane * 2 + 1 == top1) ? -INFINITY : l1;
        float bv2; int bi2;
        if (c1 > c0) { bv2 = c1; bi2 = lane * 2 + 1; } else { bv2 = c0; bi2 = lane * 2; }
        #pragma unroll
        for (int off = 16; off; off >>= 1) {
            float ov = __shfl_xor_sync(0xffffffffu, bv2, off);
            int   oi = __shfl_xor_sync(0xffffffffu, bi2, off);
            if (ov > bv2 || (ov == bv2 && oi < bi2)) { bv2 = ov; bi2 = oi; }
        }
        int top2 = bi2;

        float sel1 = (top1 & 1) ? p1 : p0;
        float pt1 = __shfl_sync(0xffffffffu, sel1, top1 >> 1);
        float sel2 = (top2 & 1) ? p1 : p0;
        float pt2 = __shfl_sync(0xffffffffu, sel2, top2 >> 1);

        float s1 = (1.0f - pt1) + pt1;
        float s2 = (1.0f - pt2) + pt2;
        float dsum = fmaxf(s1 + s2, 1e-9f);

        if (lane == 0) {
            out[OFF_IDX + t * 2]     = (float)top1;
            out[OFF_IDX + t * 2 + 1] = (float)top2;
            out[OFF_SC + t * 2]      = s1 / dsum;
            out[OFF_SC + t * 2 + 1]  = s2 / dsum;
            atomicAdd(&g_loadcnt[top1], 1);
            atomicAdd(&g_loadcnt[top2], 1);
        }
    }

    simp[warp * 64 + lane * 2]     = pimp0;
    simp[warp * 64 + lane * 2 + 1] = pimp1;
    __syncthreads();
    if (threadIdx.x < 64) {
        float a = 0.f;
        #pragma unroll
        for (int w = 0; w < 8; w++) a += simp[w * 64 + threadIdx.x];
        atomicAdd(&g_imp[threadIdx.x], a);
    }
}

// ---------------- write importance / load ----------------
__global__ void stats_out_kernel(float* __restrict__ out) {
    int e = threadIdx.x;
    out[OFF_IMP + e]  = g_imp[e] * (1.f / TOKENS);
    out[OFF_LOAD + e] = (float)g_loadcnt[e] * (1.f / TOKENS);
}

// ---------------- launch ----------------
extern "C" void kernel_launch(void* const* d_in, const int* in_sizes, int n_in,
                              void* d_out, int out_size) {
    const float* x     = (const float*)d_in[0];
    const float* Wg    = (const float*)d_in[1];
    const float* gamma = (const float*)d_in[2];
    const float* beta  = (const float*)d_in[3];
    const float* W1    = (const float*)d_in[4];
    const float* W2    = (const float*)d_in[5];
    float* out = (float*)d_out;

    cudaFuncSetAttribute(gemm_fused, cudaFuncAttributeMaxDynamicSharedMemorySize, G2_SMEM);

    prep_kernel<<<10368, 256>>>(W1, Wg, x, gamma, beta);
    dim3 g3(4, TOKENS / 128);
    gemm_fused<<<g3, 256, G2_SMEM>>>(x, W2);
    finalize_kernel<<<TOKENS / 32, 256>>>(out);
    stats_out_kernel<<<1, NEXP>>>(out);
}

// round 13
// speedup vs baseline: 1.0557x; 1.0495x over previous
#include <cuda_runtime.h>
#include <cuda_bf16.h>
#include <math.h>
#include <stdint.h>

#define TOKENS 16384
#define DDIM   2048
#define NEXP   64
#define HDIM   1024

// Output layout (float32): idx [16384*2] | scores [16384*2] | probs [16384*64] | imp [64] | load [64]
#define OFF_IDX   0
#define OFF_SC    32768
#define OFF_P     65536
#define OFF_IMP   1114112
#define OFF_LOAD  1114176

// ---------------- scratch ----------------
__device__ __nv_bfloat16 g_w1[(size_t)HDIM * DDIM];        // W1 * gamma, bf16
__device__ __nv_bfloat16 g_wg_hi[(size_t)NEXP * DDIM];
__device__ __nv_bfloat16 g_wg_lo[(size_t)NEXP * DDIM];
__device__ float g_logits[(size_t)TOKENS * NEXP];
__device__ float g_diffpre[TOKENS];
__device__ float g_mu[TOKENS];
__device__ float g_rstd[TOKENS];
__device__ float g_c1[HDIM];
__device__ float g_c2[HDIM];
__device__ float g_imp[NEXP];
__device__ int   g_loadcnt[NEXP];
__device__ int   g_fincnt;

// ---------------- shared helpers ----------------
__device__ __forceinline__ uint32_t smem_u32(const void* p) {
    uint32_t a;
    asm("{ .reg .u64 t; cvta.to.shared.u64 t, %1; cvt.u32.u64 %0, t; }" : "=r"(a) : "l"(p));
    return a;
}
__device__ __forceinline__ uint32_t g1_sw(uint32_t r, uint32_t c) {
    return r * 64 + ((c ^ ((r >> 1) & 3)) * 16);
}
__device__ __forceinline__ void ldsm_x4(uint32_t& r0, uint32_t& r1, uint32_t& r2, uint32_t& r3,
                                        uint32_t addr) {
    asm volatile("ldmatrix.sync.aligned.m8n8.x4.shared.b16 {%0,%1,%2,%3}, [%4];"
                 : "=r"(r0), "=r"(r1), "=r"(r2), "=r"(r3) : "r"(addr));
}
__device__ __forceinline__ float gelu_exact(float v) {
    return 0.5f * v * (1.0f + erff(v * 0.70710678118654752440f));
}
#define MMA_BF16(acc, a, b0, b1) \
    asm volatile( \
        "mma.sync.aligned.m16n8k16.row.col.f32.bf16.bf16.f32 " \
        "{%0,%1,%2,%3}, {%4,%5,%6,%7}, {%8,%9}, {%0,%1,%2,%3};\n" \
        : "+f"((acc)[0]), "+f"((acc)[1]), "+f"((acc)[2]), "+f"((acc)[3]) \
        : "r"((a)[0]), "r"((a)[1]), "r"((a)[2]), "r"((a)[3]), "r"(b0), "r"(b1))

// =========================================================================
// prep: W1*gamma -> bf16, Wg hi/lo, zeros, C1/C2.  grid 8192 + 128
// =========================================================================
__global__ __launch_bounds__(256)
void prep_kernel(const float* __restrict__ W1, const float* __restrict__ Wg,
                 const float* __restrict__ gamma, const float* __restrict__ beta) {
    int b = blockIdx.x;
    int tid = threadIdx.x;
    if (b < 8192) {
        int i = b * 256 + tid;
        g_w1[i] = __float2bfloat16(W1[i] * gamma[i & (DDIM - 1)]);
        if (i < NEXP * DDIM) {
            float v = Wg[i];
            __nv_bfloat16 hi = __float2bfloat16(v);
            g_wg_hi[i] = hi;
            g_wg_lo[i] = __float2bfloat16(v - __bfloat162float(hi));
        }
        if (i < TOKENS) g_diffpre[i] = 0.f;
        if (i < NEXP) { g_loadcnt[i] = 0; g_imp[i] = 0.f; }
        if (i == 0) g_fincnt = 0;
    } else {
        int n = (b - 8192) * 8 + (tid >> 5);
        int lane = tid & 31;
        const float* wr = W1 + (size_t)n * DDIM;
        float c1 = 0.f, c2 = 0.f;
        #pragma unroll 8
        for (int k = 0; k < 64; k++) {
            int d = lane + k * 32;
            float w = wr[d];
            c1 += w * gamma[d];
            c2 += w * beta[d];
        }
        #pragma unroll
        for (int off = 16; off; off >>= 1) {
            c1 += __shfl_xor_sync(0xffffffffu, c1, off);
            c2 += __shfl_xor_sync(0xffffffffu, c2, off);
        }
        if (lane == 0) { g_c1[n] = c1; g_c2[n] = c2; }
    }
}

// =========================================================================
// ln_logits: LN stats + base-logits GEMM (bf16x3), ldmatrix + swizzled smem,
// double-buffered, one barrier per chunk. CTA = 128 tokens, 512 threads.
// Stage layout (bytes): Ah[0,8192) Al[8192,16384) Wh[16384,20480) Wl[20480,24576)
// =========================================================================
#define LN_STG_B 24576
#define LN_SMEM  (2 * LN_STG_B + 4096)

__global__ __launch_bounds__(512)
void ln_logits(const float* __restrict__ x) {
    extern __shared__ __align__(128) char lsm[];
    uint32_t sb = smem_u32(lsm);
    float* sS = (float*)(lsm + 2 * LN_STG_B);
    float* sQ = sS + 512;

    int tile = blockIdx.x;
    int tid = threadIdx.x;
    int warp = tid >> 5, lane = tid & 31;
    const float* xb = x + (size_t)tile * 128 * DDIM;

    int r0 = tid >> 2;          // 0..127 token row
    int q  = tid & 3;           // 16B chunk within 64B row
    int wt = tid & 255;         // Wg loader index
    int wmat = tid >> 8;        // 0 = hi, 1 = lo
    int wr = wt >> 2, wc = wt & 3;
    int wm  = (warp & 7) * 16;
    int wn2 = (warp >> 3) * 32;
    int lrow = lane & 15;
    int lsel = lane >> 4;

    float s = 0.f, qq = 0.f;
    float acc[4][4];
    #pragma unroll
    for (int j = 0; j < 4; j++)
        #pragma unroll
        for (int r = 0; r < 4; r++) acc[j][r] = 0.f;

    const __nv_bfloat16* wsrc = wmat ? g_wg_lo : g_wg_hi;

    float4 v0 = *(const float4*)&xb[(size_t)r0 * DDIM + q * 8];
    float4 v1 = *(const float4*)&xb[(size_t)r0 * DDIM + q * 8 + 4];
    uint4 wv = *(const uint4*)&wsrc[(size_t)wr * DDIM + wc * 8];

    // convert chunk 0 -> stage 0
    {
        uint32_t ao = g1_sw((uint32_t)r0, (uint32_t)q);
        s += v0.x + v0.y + v0.z + v0.w + v1.x + v1.y + v1.z + v1.w;
        qq += v0.x*v0.x + v0.y*v0.y + v0.z*v0.z + v0.w*v0.w
            + v1.x*v1.x + v1.y*v1.y + v1.z*v1.z + v1.w*v1.w;
        __align__(16) __nv_bfloat16 hb[8], lb[8];
        float vv[8] = {v0.x, v0.y, v0.z, v0.w, v1.x, v1.y, v1.z, v1.w};
        #pragma unroll
        for (int i = 0; i < 8; i++) {
            __nv_bfloat16 b = __float2bfloat16(vv[i]);
            hb[i] = b;
            lb[i] = __float2bfloat16(vv[i] - __bfloat162float(b));
        }
        *(uint4*)(lsm + ao) = *(uint4*)hb;
        *(uint4*)(lsm + 8192 + ao) = *(uint4*)lb;
        *(uint4*)(lsm + 16384 + wmat * 4096 + g1_sw((uint32_t)wr, (uint32_t)wc)) = wv;
    }
    __syncthreads();

    #pragma unroll 2
    for (int kc = 0; kc < 64; kc++) {
        if (kc < 63) {
            int k0n = (kc + 1) * 32;
            v0 = *(const float4*)&xb[(size_t)r0 * DDIM + k0n + q * 8];
            v1 = *(const float4*)&xb[(size_t)r0 * DDIM + k0n + q * 8 + 4];
            wv = *(const uint4*)&wsrc[(size_t)wr * DDIM + k0n + wc * 8];
        }

        // MMA from stage kc&1
        {
            uint32_t st = sb + (kc & 1) * LN_STG_B;
            #pragma unroll
            for (int ks = 0; ks < 2; ks++) {
                uint32_t ao = g1_sw((uint32_t)(wm + lrow), (uint32_t)(ks * 2 + lsel));
                uint32_t ah[4], al[4];
                ldsm_x4(ah[0], ah[1], ah[2], ah[3], st + ao);
                ldsm_x4(al[0], al[1], al[2], al[3], st + 8192 + ao);
                uint32_t bh[4][2], bl[4][2];
                #pragma unroll
                for (int jb = 0; jb < 2; jb++) {
                    uint32_t wo = g1_sw((uint32_t)(wn2 + jb * 16 + lrow),
                                        (uint32_t)(ks * 2 + lsel));
                    uint32_t t0, t1, t2, t3;
                    ldsm_x4(t0, t1, t2, t3, st + 16384 + wo);
                    bh[jb * 2][0] = t0;     bh[jb * 2][1] = t2;
                    bh[jb * 2 + 1][0] = t1; bh[jb * 2 + 1][1] = t3;
                    ldsm_x4(t0, t1, t2, t3, st + 20480 + wo);
                    bl[jb * 2][0] = t0;     bl[jb * 2][1] = t2;
                    bl[jb * 2 + 1][0] = t1; bl[jb * 2 + 1][1] = t3;
                }
                #pragma unroll
                for (int j = 0; j < 4; j++) {
                    MMA_BF16(acc[j], ah, bh[j][0], bh[j][1]);
                    MMA_BF16(acc[j], ah, bl[j][0], bl[j][1]);
                    MMA_BF16(acc[j], al, bh[j][0], bh[j][1]);
                }
            }
        }

        // convert chunk kc+1 -> stage (kc+1)&1
        if (kc < 63) {
            char* stn = lsm + ((kc + 1) & 1) * LN_STG_B;
            uint32_t ao = g1_sw((uint32_t)r0, (uint32_t)q);
            s += v0.x + v0.y + v0.z + v0.w + v1.x + v1.y + v1.z + v1.w;
            qq += v0.x*v0.x + v0.y*v0.y + v0.z*v0.z + v0.w*v0.w
                + v1.x*v1.x + v1.y*v1.y + v1.z*v1.z + v1.w*v1.w;
            __align__(16) __nv_bfloat16 hb[8], lb[8];
            float vv[8] = {v0.x, v0.y, v0.z, v0.w, v1.x, v1.y, v1.z, v1.w};
            #pragma unroll
            for (int i = 0; i < 8; i++) {
                __nv_bfloat16 b = __float2bfloat16(vv[i]);
                hb[i] = b;
                lb[i] = __float2bfloat16(vv[i] - __bfloat162float(b));
            }
            *(uint4*)(stn + ao) = *(uint4*)hb;
            *(uint4*)(stn + 8192 + ao) = *(uint4*)lb;
            *(uint4*)(stn + 16384 + wmat * 4096 + g1_sw((uint32_t)wr, (uint32_t)wc)) = wv;
        }
        __syncthreads();
    }

    sS[r0 * 4 + q] = s;
    sQ[r0 * 4 + q] = qq;
    __syncthreads();
    if (tid < 128) {
        float ts = sS[tid*4] + sS[tid*4+1] + sS[tid*4+2] + sS[tid*4+3];
        float tq = sQ[tid*4] + sQ[tid*4+1] + sQ[tid*4+2] + sQ[tid*4+3];
        float mean = ts * (1.f / DDIM);
        float var  = tq * (1.f / DDIM) - mean * mean;
        g_mu[tile * 128 + tid]   = mean;
        g_rstd[tile * 128 + tid] = rsqrtf(var + 1e-5f);
    }

    #pragma unroll
    for (int j = 0; j < 4; j++) {
        int row = tile * 128 + wm + (lane >> 2);
        int col = wn2 + j * 8 + (lane & 3) * 2;
        float2 c01; c01.x = acc[j][0]; c01.y = acc[j][1];
        float2 c23; c23.x = acc[j][2]; c23.y = acc[j][3];
        *(float2*)&g_logits[(size_t)row * NEXP + col] = c01;
        *(float2*)&g_logits[(size_t)(row + 8) * NEXP + col] = c23;
    }
}

// =========================================================================
// gemm1: BM=128 x BN=256 x BK=32, bf16 MMA fp32 accum. A = bf16(x) raw,
// gamma folded into W1; epilogue h1 = rs*acc - rs*mu*C1 + C2.
// =========================================================================
#define G2_STAGES 3
#define G2_BK     32
#define G2_BN     256
#define G2_BBYTES 16384
#define G2_ABYTES 8192
#define G2_A_OFF  (G2_STAGES * G2_BBYTES)
#define G2_SMEM   (G2_A_OFF + 2 * G2_ABYTES)
#define G2_CHUNKS (DDIM / G2_BK)

__device__ __forceinline__ void g2_stage_B(uint32_t sB, const __nv_bfloat16* Bg,
                                           int k0, int tid) {
    #pragma unroll
    for (int i = 0; i < 4; i++) {
        int idx = tid + i * 256;
        int r = idx >> 2, c = idx & 3;
        uint32_t dst = sB + g1_sw(r, c);
        asm volatile("cp.async.cg.shared.global [%0], [%1], 16;\n"
                     :: "r"(dst), "l"(Bg + (size_t)r * DDIM + k0 + c * 8));
    }
    asm volatile("cp.async.commit_group;\n");
}

__global__ __launch_bounds__(256, 1)
void gemm1_mma(const float* __restrict__ x, const float* __restrict__ W2) {
    extern __shared__ __align__(128) char g1sm[];
    uint32_t sb = smem_u32(g1sm);
    int tid = threadIdx.x;
    int warp = tid >> 5, lane = tid & 31;
    int bn = blockIdx.x, bm = blockIdx.y;
    int wm = (warp & 1) * 64;
    int wn = (warp >> 1) * 64;

    const float* xb = x + (size_t)(bm * 128) * DDIM;
    const __nv_bfloat16* Bg = g_w1 + (size_t)(bn * G2_BN) * DDIM;

    int r0 = tid >> 1;
    int hsel = tid & 1;
    int lrow = lane & 15;
    int lsel = lane >> 4;

    float acc[4][8][4];
    #pragma unroll
    for (int i = 0; i < 4; i++)
        #pragma unroll
        for (int j = 0; j < 8; j++)
            #pragma unroll
            for (int r = 0; r < 4; r++) acc[i][j][r] = 0.f;

    g2_stage_B(sb + 0 * G2_BBYTES, Bg, 0, tid);
    g2_stage_B(sb + 1 * G2_BBYTES, Bg, G2_BK, tid);
    float4 xv[4];
    #pragma unroll
    for (int i = 0; i < 4; i++)
        xv[i] = *(const float4*)&xb[(size_t)r0 * DDIM + hsel * 16 + i * 4];

    #pragma unroll 1
    for (int c = 0; c < G2_CHUNKS; c++) {
        if (c + 2 < G2_CHUNKS)
            g2_stage_B(sb + ((c + 2) % G2_STAGES) * G2_BBYTES, Bg, (c + 2) * G2_BK, tid);

        {
            uint32_t sA = sb + G2_A_OFF + (c & 1) * G2_ABYTES;
            __align__(16) __nv_bfloat16 ob[16];
            #pragma unroll
            for (int i = 0; i < 4; i++) {
                __nv_bfloat162 p0 = __floats2bfloat162_rn(xv[i].x, xv[i].y);
                __nv_bfloat162 p1 = __floats2bfloat162_rn(xv[i].z, xv[i].w);
                *(uint32_t*)&ob[i * 4]     = *(uint32_t*)&p0;
                *(uint32_t*)&ob[i * 4 + 2] = *(uint32_t*)&p1;
            }
            #pragma unroll
            for (int j = 0; j < 2; j++) {
                uint32_t dst = sA + g1_sw((uint32_t)r0, (uint32_t)(hsel * 2 + j));
                *(uint4*)(g1sm + (dst - sb)) = *(uint4*)&ob[j * 8];
            }
        }

        if (c + 1 < G2_CHUNKS) {
            #pragma unroll
            for (int i = 0; i < 4; i++)
                xv[i] = *(const float4*)&xb[(size_t)r0 * DDIM + (c + 1) * G2_BK + hsel * 16 + i * 4];
        }

        if (c + 2 < G2_CHUNKS) {
            asm volatile("cp.async.wait_group 2;\n");
        } else if (c + 2 == G2_CHUNKS) {
            asm volatile("cp.async.wait_group 1;\n");
        } else {
            asm volatile("cp.async.wait_group 0;\n");
        }
        __syncthreads();

        uint32_t sA = sb + G2_A_OFF + (c & 1) * G2_ABYTES;
        uint32_t sB = sb + (c % G2_STAGES) * G2_BBYTES;

        #pragma unroll
        for (int ks = 0; ks < 2; ks++) {
            uint32_t af[4][4], bf[8][2];
            #pragma unroll
            for (int i = 0; i < 4; i++) {
                uint32_t r = (uint32_t)(wm + i * 16 + lrow);
                ldsm_x4(af[i][0], af[i][1], af[i][2], af[i][3],
                        sA + g1_sw(r, (uint32_t)(ks * 2 + lsel)));
            }
            #pragma unroll
            for (int jb = 0; jb < 4; jb++) {
                uint32_t r = (uint32_t)(wn + jb * 16 + lrow);
                uint32_t q0, q1, q2, q3;
                ldsm_x4(q0, q1, q2, q3, sB + g1_sw(r, (uint32_t)(ks * 2 + lsel)));
                bf[jb * 2][0] = q0;     bf[jb * 2][1] = q2;
                bf[jb * 2 + 1][0] = q1; bf[jb * 2 + 1][1] = q3;
            }
            #pragma unroll
            for (int i = 0; i < 4; i++)
                #pragma unroll
                for (int j = 0; j < 8; j++)
                    MMA_BF16(acc[i][j], af[i], bf[j][0], bf[j][1]);
        }
        __syncthreads();
    }

    // epilogue: h1 = rs*acc - rs*mu*C1 + C2; gelu*W2; reduce
    float part0[4] = {0.f, 0.f, 0.f, 0.f};
    float part1[4] = {0.f, 0.f, 0.f, 0.f};
    float rs0[4], rm0[4], rs1[4], rm1[4];
    #pragma unroll
    for (int i = 0; i < 4; i++) {
        int m0 = bm * 128 + wm + i * 16 + (lane >> 2);
        rs0[i] = g_rstd[m0];     rm0[i] = rs0[i] * g_mu[m0];
        rs1[i] = g_rstd[m0 + 8]; rm1[i] = rs1[i] * g_mu[m0 + 8];
    }
    #pragma unroll
    for (int j = 0; j < 8; j++) {
        int n = bn * G2_BN + wn + j * 8 + (lane & 3) * 2;
        float2 c1 = *(const float2*)&g_c1[n];
        float2 c2 = *(const float2*)&g_c2[n];
        float2 w2 = *(const float2*)&W2[n];
        #pragma unroll
        for (int i = 0; i < 4; i++) {
            float h00 = rs0[i] * acc[i][j][0] - rm0[i] * c1.x + c2.x;
            float h01 = rs0[i] * acc[i][j][1] - rm0[i] * c1.y + c2.y;
            float h10 = rs1[i] * acc[i][j][2] - rm1[i] * c1.x + c2.x;
            float h11 = rs1[i] * acc[i][j][3] - rm1[i] * c1.y + c2.y;
            part0[i] += gelu_exact(h00) * w2.x + gelu_exact(h01) * w2.y;
            part1[i] += gelu_exact(h10) * w2.x + gelu_exact(h11) * w2.y;
        }
    }
    #pragma unroll
    for (int i = 0; i < 4; i++) {
        part0[i] += __shfl_xor_sync(0xffffffffu, part0[i], 1);
        part0[i] += __shfl_xor_sync(0xffffffffu, part0[i], 2);
        part1[i] += __shfl_xor_sync(0xffffffffu, part1[i], 1);
        part1[i] += __shfl_xor_sync(0xffffffffu, part1[i], 2);
    }
    if ((lane & 3) == 0) {
        int mbase = bm * 128 + wm + (lane >> 2);
        #pragma unroll
        for (int i = 0; i < 4; i++) {
            atomicAdd(&g_diffpre[mbase + i * 16], part0[i]);
            atomicAdd(&g_diffpre[mbase + i * 16 + 8], part1[i]);
        }
    }
}

// ---------------- finalize: 4 tokens/warp + fused importance + last-block stats ----------------
__global__ __launch_bounds__(256)
void finalize_kernel(float* __restrict__ out) {
    __shared__ float simp[8 * 64];
    __shared__ int is_last;
    int warp = threadIdx.x >> 5;
    int lane = threadIdx.x & 31;
    int tbase = blockIdx.x * 32 + warp * 4;

    float2 lg[4]; float dp[4];
    #pragma unroll
    for (int tt = 0; tt < 4; tt++) {
        lg[tt] = *(const float2*)&g_logits[(size_t)(tbase + tt) * NEXP + lane * 2];
        dp[tt] = g_diffpre[tbase + tt];
    }

    float pimp0 = 0.f, pimp1 = 0.f;
    #pragma unroll
    for (int tt = 0; tt < 4; tt++) {
        int t = tbase + tt;
        float diff = 1.f / (1.f + __expf(-dp[tt]));
        float rden = 1.f / (1.f + diff);
        float l0 = lg[tt].x * rden;
        float l1 = lg[tt].y * rden;

        float e0 = __expf(l0), e1 = __expf(l1);
        float sum = e0 + e1;
        #pragma unroll
        for (int off = 16; off; off >>= 1) sum += __shfl_xor_sync(0xffffffffu, sum, off);
        float inv = 1.f / sum;
        float p0 = e0 * inv, p1 = e1 * inv;
        *(float2*)&out[OFF_P + (size_t)t * NEXP + lane * 2] = make_float2(p0, p1);
        pimp0 += p0; pimp1 += p1;

        float bv; int bi;
        if (l1 > l0) { bv = l1; bi = lane * 2 + 1; } else { bv = l0; bi = lane * 2; }
        #pragma unroll
        for (int off = 16; off; off >>= 1) {
            float ov = __shfl_xor_sync(0xffffffffu, bv, off);
            int   oi = __shfl_xor_sync(0xffffffffu, bi, off);
            if (ov > bv || (ov == bv && oi < bi)) { bv = ov; bi = oi; }
        }
        int top1 = bi;
        float c0 = (lane * 2     == top1) ? -INFINITY : l0;
        float c1 = (lane * 2 + 1 == top1) ? -INFINITY : l1;
        float bv2; int bi2;
        if (c1 > c0) { bv2 = c1; bi2 = lane * 2 + 1; } else { bv2 = c0; bi2 = lane * 2; }
        #pragma unroll
        for (int off = 16; off; off >>= 1) {
            float ov = __shfl_xor_sync(0xffffffffu, bv2, off);
            int   oi = __shfl_xor_sync(0xffffffffu, bi2, off);
            if (ov > bv2 || (ov == bv2 && oi < bi2)) { bv2 = ov; bi2 = oi; }
        }
        int top2 = bi2;

        float sel1 = (top1 & 1) ? p1 : p0;
        float pt1 = __shfl_sync(0xffffffffu, sel1, top1 >> 1);
        float sel2 = (top2 & 1) ? p1 : p0;
        float pt2 = __shfl_sync(0xffffffffu, sel2, top2 >> 1);

        float s1 = (1.0f - pt1) + pt1;
        float s2 = (1.0f - pt2) + pt2;
        float dsum = fmaxf(s1 + s2, 1e-9f);

        if (lane == 0) {
            out[OFF_IDX + t * 2]     = (float)top1;
            out[OFF_IDX + t * 2 + 1] = (float)top2;
            out[OFF_SC + t * 2]      = s1 / dsum;
            out[OFF_SC + t * 2 + 1]  = s2 / dsum;
            atomicAdd(&g_loadcnt[top1], 1);
            atomicAdd(&g_loadcnt[top2], 1);
        }
    }

    simp[warp * 64 + lane * 2]     = pimp0;
    simp[warp * 64 + lane * 2 + 1] = pimp1;
    __syncthreads();
    if (threadIdx.x < 64) {
        float a = 0.f;
        #pragma unroll
        for (int w = 0; w < 8; w++) a += simp[w * 64 + threadIdx.x];
        atomicAdd(&g_imp[threadIdx.x], a);
    }

    // last finished block writes importance / load outputs
    __syncthreads();
    if (threadIdx.x == 0) {
        __threadfence();
        is_last = (atomicAdd(&g_fincnt, 1) == (int)gridDim.x - 1);
    }
    __syncthreads();
    if (is_last && threadIdx.x < 64) {
        __threadfence();
        int e = threadIdx.x;
        out[OFF_IMP + e]  = g_imp[e] * (1.f / TOKENS);
        out[OFF_LOAD + e] = (float)g_loadcnt[e] * (1.f / TOKENS);
    }
}

// ---------------- launch ----------------
extern "C" void kernel_launch(void* const* d_in, const int* in_sizes, int n_in,
                              void* d_out, int out_size) {
    const float* x     = (const float*)d_in[0];
    const float* Wg    = (const float*)d_in[1];
    const float* gamma = (const float*)d_in[2];
    const float* beta  = (const float*)d_in[3];
    const float* W1    = (const float*)d_in[4];
    const float* W2    = (const float*)d_in[5];
    float* out = (float*)d_out;

    cudaFuncSetAttribute(gemm1_mma, cudaFuncAttributeMaxDynamicSharedMemorySize, G2_SMEM);
    cudaFuncSetAttribute(ln_logits, cudaFuncAttributeMaxDynamicSharedMemorySize, LN_SMEM);

    prep_kernel<<<8320, 256>>>(W1, Wg, gamma, beta);
    ln_logits<<<TOKENS / 128, 512, LN_SMEM>>>(x);
    dim3 g3(HDIM / G2_BN, TOKENS / 128);
    gemm1_mma<<<g3, 256, G2_SMEM>>>(x, W2);
    finalize_kernel<<<TOKENS / 32, 256>>>(out);
}

// round 14
// speedup vs baseline: 1.0817x; 1.0246x over previous
#include <cuda_runtime.h>
#include <cuda_bf16.h>
#include <math.h>
#include <stdint.h>

#define TOKENS 16384
#define DDIM   2048
#define NEXP   64
#define HDIM   1024

// Output layout (float32): idx [16384*2] | scores [16384*2] | probs [16384*64] | imp [64] | load [64]
#define OFF_IDX   0
#define OFF_SC    32768
#define OFF_P     65536
#define OFF_IMP   1114112
#define OFF_LOAD  1114176

// ---------------- scratch ----------------
__device__ __nv_bfloat16 g_w1[(size_t)HDIM * DDIM];        // W1 * gamma, bf16
__device__ __nv_bfloat16 g_wg_hi[(size_t)NEXP * DDIM];
__device__ __nv_bfloat16 g_wg_lo[(size_t)NEXP * DDIM];
__device__ float g_logits[(size_t)TOKENS * NEXP];
__device__ float g_diffpre[TOKENS];
__device__ float g_mu[TOKENS];
__device__ float g_rstd[TOKENS];
__device__ float g_c1[HDIM];
__device__ float g_c2[HDIM];
__device__ float g_imp[NEXP];
__device__ int   g_loadcnt[NEXP];
__device__ int   g_fincnt;

// ---------------- shared helpers ----------------
__device__ __forceinline__ uint32_t smem_u32(const void* p) {
    uint32_t a;
    asm("{ .reg .u64 t; cvta.to.shared.u64 t, %1; cvt.u32.u64 %0, t; }" : "=r"(a) : "l"(p));
    return a;
}
__device__ __forceinline__ uint32_t g1_sw(uint32_t r, uint32_t c) {
    return r * 64 + ((c ^ ((r >> 1) & 3)) * 16);
}
__device__ __forceinline__ void ldsm_x4(uint32_t& r0, uint32_t& r1, uint32_t& r2, uint32_t& r3,
                                        uint32_t addr) {
    asm volatile("ldmatrix.sync.aligned.m8n8.x4.shared.b16 {%0,%1,%2,%3}, [%4];"
                 : "=r"(r0), "=r"(r1), "=r"(r2), "=r"(r3) : "r"(addr));
}
__device__ __forceinline__ float gelu_exact(float v) {
    return 0.5f * v * (1.0f + erff(v * 0.70710678118654752440f));
}
#define MMA_BF16(acc, a, b0, b1) \
    asm volatile( \
        "mma.sync.aligned.m16n8k16.row.col.f32.bf16.bf16.f32 " \
        "{%0,%1,%2,%3}, {%4,%5,%6,%7}, {%8,%9}, {%0,%1,%2,%3};\n" \
        : "+f"((acc)[0]), "+f"((acc)[1]), "+f"((acc)[2]), "+f"((acc)[3]) \
        : "r"((a)[0]), "r"((a)[1]), "r"((a)[2]), "r"((a)[3]), "r"(b0), "r"(b1))

// =========================================================================
// prep: W1*gamma -> bf16, Wg hi/lo, zeros, C1/C2.  grid 8192 + 128
// =========================================================================
__global__ __launch_bounds__(256)
void prep_kernel(const float* __restrict__ W1, const float* __restrict__ Wg,
                 const float* __restrict__ gamma, const float* __restrict__ beta) {
    int b = blockIdx.x;
    int tid = threadIdx.x;
    if (b < 8192) {
        int i = b * 256 + tid;
        g_w1[i] = __float2bfloat16(W1[i] * gamma[i & (DDIM - 1)]);
        if (i < NEXP * DDIM) {
            float v = Wg[i];
            __nv_bfloat16 hi = __float2bfloat16(v);
            g_wg_hi[i] = hi;
            g_wg_lo[i] = __float2bfloat16(v - __bfloat162float(hi));
        }
        if (i < TOKENS) g_diffpre[i] = 0.f;
        if (i < NEXP) { g_loadcnt[i] = 0; g_imp[i] = 0.f; }
        if (i == 0) g_fincnt = 0;
    } else {
        int n = (b - 8192) * 8 + (tid >> 5);
        int lane = tid & 31;
        const float* wr = W1 + (size_t)n * DDIM;
        float c1 = 0.f, c2 = 0.f;
        #pragma unroll 8
        for (int k = 0; k < 64; k++) {
            int d = lane + k * 32;
            float w = wr[d];
            c1 += w * gamma[d];
            c2 += w * beta[d];
        }
        #pragma unroll
        for (int off = 16; off; off >>= 1) {
            c1 += __shfl_xor_sync(0xffffffffu, c1, off);
            c2 += __shfl_xor_sync(0xffffffffu, c2, off);
        }
        if (lane == 0) { g_c1[n] = c1; g_c2[n] = c2; }
    }
}

// =========================================================================
// ln_logits: 64-token tiles, 256 threads, 2 CTAs/SM for barrier overlap.
// LN stats + base-logits GEMM (bf16x3), ldmatrix + swizzled smem, dbl-buffered.
// Stage layout (bytes): Ah[0,4096) Al[4096,8192) Wh[8192,12288) Wl[12288,16384)
// =========================================================================
#define LN_STG_B 16384
#define LN_SMEM  (2 * LN_STG_B + 2048)

__global__ __launch_bounds__(256, 2)
void ln_logits(const float* __restrict__ x) {
    extern __shared__ __align__(128) char lsm[];
    uint32_t sb = smem_u32(lsm);
    float* sS = (float*)(lsm + 2 * LN_STG_B);
    float* sQ = sS + 256;

    int tile = blockIdx.x;
    int tid = threadIdx.x;
    int warp = tid >> 5, lane = tid & 31;
    const float* xb = x + (size_t)tile * 64 * DDIM;

    int r0 = tid >> 2;          // 0..63 token row
    int q  = tid & 3;           // 16B chunk within 64B row
    int wr = tid >> 2;          // 0..63 Wg row
    int wc = tid & 3;
    int wm  = (warp & 3) * 16;  // warp M offset (64 rows)
    int wn2 = (warp >> 2) * 32; // warp N offset (0/32)
    int lrow = lane & 15;
    int lsel = lane >> 4;

    float s = 0.f, qq = 0.f;
    float acc[4][4];
    #pragma unroll
    for (int j = 0; j < 4; j++)
        #pragma unroll
        for (int r = 0; r < 4; r++) acc[j][r] = 0.f;

    float4 v0 = *(const float4*)&xb[(size_t)r0 * DDIM + q * 8];
    float4 v1 = *(const float4*)&xb[(size_t)r0 * DDIM + q * 8 + 4];
    uint4 wvh = *(const uint4*)&g_wg_hi[(size_t)wr * DDIM + wc * 8];
    uint4 wvl = *(const uint4*)&g_wg_lo[(size_t)wr * DDIM + wc * 8];

    // convert chunk 0 -> stage 0
    {
        uint32_t ao = g1_sw((uint32_t)r0, (uint32_t)q);
        s += v0.x + v0.y + v0.z + v0.w + v1.x + v1.y + v1.z + v1.w;
        qq += v0.x*v0.x + v0.y*v0.y + v0.z*v0.z + v0.w*v0.w
            + v1.x*v1.x + v1.y*v1.y + v1.z*v1.z + v1.w*v1.w;
        __align__(16) __nv_bfloat16 hb[8], lb[8];
        float vv[8] = {v0.x, v0.y, v0.z, v0.w, v1.x, v1.y, v1.z, v1.w};
        #pragma unroll
        for (int i = 0; i < 8; i++) {
            __nv_bfloat16 b = __float2bfloat16(vv[i]);
            hb[i] = b;
            lb[i] = __float2bfloat16(vv[i] - __bfloat162float(b));
        }
        *(uint4*)(lsm + ao) = *(uint4*)hb;
        *(uint4*)(lsm + 4096 + ao) = *(uint4*)lb;
        uint32_t wo = g1_sw((uint32_t)wr, (uint32_t)wc);
        *(uint4*)(lsm + 8192 + wo) = wvh;
        *(uint4*)(lsm + 12288 + wo) = wvl;
    }
    __syncthreads();

    #pragma unroll 2
    for (int kc = 0; kc < 64; kc++) {
        if (kc < 63) {
            int k0n = (kc + 1) * 32;
            v0 = *(const float4*)&xb[(size_t)r0 * DDIM + k0n + q * 8];
            v1 = *(const float4*)&xb[(size_t)r0 * DDIM + k0n + q * 8 + 4];
            wvh = *(const uint4*)&g_wg_hi[(size_t)wr * DDIM + k0n + wc * 8];
            wvl = *(const uint4*)&g_wg_lo[(size_t)wr * DDIM + k0n + wc * 8];
        }

        // MMA from stage kc&1
        {
            uint32_t st = sb + (kc & 1) * LN_STG_B;
            #pragma unroll
            for (int ks = 0; ks < 2; ks++) {
                uint32_t ao = g1_sw((uint32_t)(wm + lrow), (uint32_t)(ks * 2 + lsel));
                uint32_t ah[4], al[4];
                ldsm_x4(ah[0], ah[1], ah[2], ah[3], st + ao);
                ldsm_x4(al[0], al[1], al[2], al[3], st + 4096 + ao);
                uint32_t bh[4][2], bl[4][2];
                #pragma unroll
                for (int jb = 0; jb < 2; jb++) {
                    uint32_t wo = g1_sw((uint32_t)(wn2 + jb * 16 + lrow),
                                        (uint32_t)(ks * 2 + lsel));
                    uint32_t t0, t1, t2, t3;
                    ldsm_x4(t0, t1, t2, t3, st + 8192 + wo);
                    bh[jb * 2][0] = t0;     bh[jb * 2][1] = t2;
                    bh[jb * 2 + 1][0] = t1; bh[jb * 2 + 1][1] = t3;
                    ldsm_x4(t0, t1, t2, t3, st + 12288 + wo);
                    bl[jb * 2][0] = t0;     bl[jb * 2][1] = t2;
                    bl[jb * 2 + 1][0] = t1; bl[jb * 2 + 1][1] = t3;
                }
                #pragma unroll
                for (int j = 0; j < 4; j++) {
                    MMA_BF16(acc[j], ah, bh[j][0], bh[j][1]);
                    MMA_BF16(acc[j], ah, bl[j][0], bl[j][1]);
                    MMA_BF16(acc[j], al, bh[j][0], bh[j][1]);
                }
            }
        }

        // convert chunk kc+1 -> stage (kc+1)&1
        if (kc < 63) {
            char* stn = lsm + ((kc + 1) & 1) * LN_STG_B;
            uint32_t ao = g1_sw((uint32_t)r0, (uint32_t)q);
            s += v0.x + v0.y + v0.z + v0.w + v1.x + v1.y + v1.z + v1.w;
            qq += v0.x*v0.x + v0.y*v0.y + v0.z*v0.z + v0.w*v0.w
                + v1.x*v1.x + v1.y*v1.y + v1.z*v1.z + v1.w*v1.w;
            __align__(16) __nv_bfloat16 hb[8], lb[8];
            float vv[8] = {v0.x, v0.y, v0.z, v0.w, v1.x, v1.y, v1.z, v1.w};
            #pragma unroll
            for (int i = 0; i < 8; i++) {
                __nv_bfloat16 b = __float2bfloat16(vv[i]);
                hb[i] = b;
                lb[i] = __float2bfloat16(vv[i] - __bfloat162float(b));
            }
            *(uint4*)(stn + ao) = *(uint4*)hb;
            *(uint4*)(stn + 4096 + ao) = *(uint4*)lb;
            uint32_t wo = g1_sw((uint32_t)wr, (uint32_t)wc);
            *(uint4*)(stn + 8192 + wo) = wvh;
            *(uint4*)(stn + 12288 + wo) = wvl;
        }
        __syncthreads();
    }

    sS[r0 * 4 + q] = s;
    sQ[r0 * 4 + q] = qq;
    __syncthreads();
    if (tid < 64) {
        float ts = sS[tid*4] + sS[tid*4+1] + sS[tid*4+2] + sS[tid*4+3];
        float tq = sQ[tid*4] + sQ[tid*4+1] + sQ[tid*4+2] + sQ[tid*4+3];
        float mean = ts * (1.f / DDIM);
        float var  = tq * (1.f / DDIM) - mean * mean;
        g_mu[tile * 64 + tid]   = mean;
        g_rstd[tile * 64 + tid] = rsqrtf(var + 1e-5f);
    }

    #pragma unroll
    for (int j = 0; j < 4; j++) {
        int row = tile * 64 + wm + (lane >> 2);
        int col = wn2 + j * 8 + (lane & 3) * 2;
        float2 c01; c01.x = acc[j][0]; c01.y = acc[j][1];
        float2 c23; c23.x = acc[j][2]; c23.y = acc[j][3];
        *(float2*)&g_logits[(size_t)row * NEXP + col] = c01;
        *(float2*)&g_logits[(size_t)(row + 8) * NEXP + col] = c23;
    }
}

// =========================================================================
// gemm1 (R13): BM=128 x BN=256 x BK=32, bf16 MMA fp32 accum. A = bf16(x) raw,
// gamma folded into W1; epilogue h1 = rs*acc - rs*mu*C1 + C2.
// =========================================================================
#define G2_STAGES 3
#define G2_BK     32
#define G2_BN     256
#define G2_BBYTES 16384
#define G2_ABYTES 8192
#define G2_A_OFF  (G2_STAGES * G2_BBYTES)
#define G2_SMEM   (G2_A_OFF + 2 * G2_ABYTES)
#define G2_CHUNKS (DDIM / G2_BK)

__device__ __forceinline__ void g2_stage_B(uint32_t sB, const __nv_bfloat16* Bg,
                                           int k0, int tid) {
    #pragma unroll
    for (int i = 0; i < 4; i++) {
        int idx = tid + i * 256;
        int r = idx >> 2, c = idx & 3;
        uint32_t dst = sB + g1_sw(r, c);
        asm volatile("cp.async.cg.shared.global [%0], [%1], 16;\n"
                     :: "r"(dst), "l"(Bg + (size_t)r * DDIM + k0 + c * 8));
    }
    asm volatile("cp.async.commit_group;\n");
}

__global__ __launch_bounds__(256, 1)
void gemm1_mma(const float* __restrict__ x, const float* __restrict__ W2) {
    extern __shared__ __align__(128) char g1sm[];
    uint32_t sb = smem_u32(g1sm);
    int tid = threadIdx.x;
    int warp = tid >> 5, lane = tid & 31;
    int bn = blockIdx.x, bm = blockIdx.y;
    int wm = (warp & 1) * 64;
    int wn = (warp >> 1) * 64;

    const float* xb = x + (size_t)(bm * 128) * DDIM;
    const __nv_bfloat16* Bg = g_w1 + (size_t)(bn * G2_BN) * DDIM;

    int r0 = tid >> 1;
    int hsel = tid & 1;
    int lrow = lane & 15;
    int lsel = lane >> 4;

    float acc[4][8][4];
    #pragma unroll
    for (int i = 0; i < 4; i++)
        #pragma unroll
        for (int j = 0; j < 8; j++)
            #pragma unroll
            for (int r = 0; r < 4; r++) acc[i][j][r] = 0.f;

    g2_stage_B(sb + 0 * G2_BBYTES, Bg, 0, tid);
    g2_stage_B(sb + 1 * G2_BBYTES, Bg, G2_BK, tid);
    float4 xv[4];
    #pragma unroll
    for (int i = 0; i < 4; i++)
        xv[i] = *(const float4*)&xb[(size_t)r0 * DDIM + hsel * 16 + i * 4];

    #pragma unroll 1
    for (int c = 0; c < G2_CHUNKS; c++) {
        if (c + 2 < G2_CHUNKS)
            g2_stage_B(sb + ((c + 2) % G2_STAGES) * G2_BBYTES, Bg, (c + 2) * G2_BK, tid);

        {
            uint32_t sA = sb + G2_A_OFF + (c & 1) * G2_ABYTES;
            __align__(16) __nv_bfloat16 ob[16];
            #pragma unroll
            for (int i = 0; i < 4; i++) {
                __nv_bfloat162 p0 = __floats2bfloat162_rn(xv[i].x, xv[i].y);
                __nv_bfloat162 p1 = __floats2bfloat162_rn(xv[i].z, xv[i].w);
                *(uint32_t*)&ob[i * 4]     = *(uint32_t*)&p0;
                *(uint32_t*)&ob[i * 4 + 2] = *(uint32_t*)&p1;
            }
            #pragma unroll
            for (int j = 0; j < 2; j++) {
                uint32_t dst = sA + g1_sw((uint32_t)r0, (uint32_t)(hsel * 2 + j));
                *(uint4*)(g1sm + (dst - sb)) = *(uint4*)&ob[j * 8];
            }
        }

        if (c + 1 < G2_CHUNKS) {
            #pragma unroll
            for (int i = 0; i < 4; i++)
                xv[i] = *(const float4*)&xb[(size_t)r0 * DDIM + (c + 1) * G2_BK + hsel * 16 + i * 4];
        }

        if (c + 2 < G2_CHUNKS) {
            asm volatile("cp.async.wait_group 2;\n");
        } else if (c + 2 == G2_CHUNKS) {
            asm volatile("cp.async.wait_group 1;\n");
        } else {
            asm volatile("cp.async.wait_group 0;\n");
        }
        __syncthreads();

        uint32_t sA = sb + G2_A_OFF + (c & 1) * G2_ABYTES;
        uint32_t sB = sb + (c % G2_STAGES) * G2_BBYTES;

        #pragma unroll
        for (int ks = 0; ks < 2; ks++) {
            uint32_t af[4][4], bf[8][2];
            #pragma unroll
            for (int i = 0; i < 4; i++) {
                uint32_t r = (uint32_t)(wm + i * 16 + lrow);
                ldsm_x4(af[i][0], af[i][1], af[i][2], af[i][3],
                        sA + g1_sw(r, (uint32_t)(ks * 2 + lsel)));
            }
            #pragma unroll
            for (int jb = 0; jb < 4; jb++) {
                uint32_t r = (uint32_t)(wn + jb * 16 + lrow);
                uint32_t q0, q1, q2, q3;
                ldsm_x4(q0, q1, q2, q3, sB + g1_sw(r, (uint32_t)(ks * 2 + lsel)));
                bf[jb * 2][0] = q0;     bf[jb * 2][1] = q2;
                bf[jb * 2 + 1][0] = q1; bf[jb * 2 + 1][1] = q3;
            }
            #pragma unroll
            for (int i = 0; i < 4; i++)
                #pragma unroll
                for (int j = 0; j < 8; j++)
                    MMA_BF16(acc[i][j], af[i], bf[j][0], bf[j][1]);
        }
        __syncthreads();
    }

    // epilogue: h1 = rs*acc - rs*mu*C1 + C2; gelu*W2; reduce
    float part0[4] = {0.f, 0.f, 0.f, 0.f};
    float part1[4] = {0.f, 0.f, 0.f, 0.f};
    float rs0[4], rm0[4], rs1[4], rm1[4];
    #pragma unroll
    for (int i = 0; i < 4; i++) {
        int m0 = bm * 128 + wm + i * 16 + (lane >> 2);
        rs0[i] = g_rstd[m0];     rm0[i] = rs0[i] * g_mu[m0];
        rs1[i] = g_rstd[m0 + 8]; rm1[i] = rs1[i] * g_mu[m0 + 8];
    }
    #pragma unroll
    for (int j = 0; j < 8; j++) {
        int n = bn * G2_BN + wn + j * 8 + (lane & 3) * 2;
        float2 c1 = *(const float2*)&g_c1[n];
        float2 c2 = *(const float2*)&g_c2[n];
        float2 w2 = *(const float2*)&W2[n];
        #pragma unroll
        for (int i = 0; i < 4; i++) {
            float h00 = rs0[i] * acc[i][j][0] - rm0[i] * c1.x + c2.x;
            float h01 = rs0[i] * acc[i][j][1] - rm0[i] * c1.y + c2.y;
            float h10 = rs1[i] * acc[i][j][2] - rm1[i] * c1.x + c2.x;
            float h11 = rs1[i] * acc[i][j][3] - rm1[i] * c1.y + c2.y;
            part0[i] += gelu_exact(h00) * w2.x + gelu_exact(h01) * w2.y;
            part1[i] += gelu_exact(h10) * w2.x + gelu_exact(h11) * w2.y;
        }
    }
    #pragma unroll
    for (int i = 0; i < 4; i++) {
        part0[i] += __shfl_xor_sync(0xffffffffu, part0[i], 1);
        part0[i] += __shfl_xor_sync(0xffffffffu, part0[i], 2);
        part1[i] += __shfl_xor_sync(0xffffffffu, part1[i], 1);
        part1[i] += __shfl_xor_sync(0xffffffffu, part1[i], 2);
    }
    if ((lane & 3) == 0) {
        int mbase = bm * 128 + wm + (lane >> 2);
        #pragma unroll
        for (int i = 0; i < 4; i++) {
            atomicAdd(&g_diffpre[mbase + i * 16], part0[i]);
            atomicAdd(&g_diffpre[mbase + i * 16 + 8], part1[i]);
        }
    }
}

// ---------------- finalize: merged top-2 reduction, 4 tokens/warp ----------------
__global__ __launch_bounds__(256)
void finalize_kernel(float* __restrict__ out) {
    __shared__ float simp[8 * 64];
    __shared__ int is_last;
    int warp = threadIdx.x >> 5;
    int lane = threadIdx.x & 31;
    int tbase = blockIdx.x * 32 + warp * 4;

    float2 lg[4]; float dp[4];
    #pragma unroll
    for (int tt = 0; tt < 4; tt++) {
        lg[tt] = *(const float2*)&g_logits[(size_t)(tbase + tt) * NEXP + lane * 2];
        dp[tt] = g_diffpre[tbase + tt];
    }

    float pimp0 = 0.f, pimp1 = 0.f;
    #pragma unroll
    for (int tt = 0; tt < 4; tt++) {
        int t = tbase + tt;
        float diff = 1.f / (1.f + __expf(-dp[tt]));
        float rden = 1.f / (1.f + diff);
        float l0 = lg[tt].x * rden;
        float l1 = lg[tt].y * rden;

        float e0 = __expf(l0), e1 = __expf(l1);
        float sum = e0 + e1;

        // local sorted pair
        float v1, v2; int i1, i2;
        if (l1 > l0) { v1 = l1; i1 = lane * 2 + 1; v2 = l0; i2 = lane * 2; }
        else         { v1 = l0; i1 = lane * 2;     v2 = l1; i2 = lane * 2 + 1; }

        // single butterfly: sum + joint top-2 merge
        #pragma unroll
        for (int off = 16; off; off >>= 1) {
            sum += __shfl_xor_sync(0xffffffffu, sum, off);
            float qv1 = __shfl_xor_sync(0xffffffffu, v1, off);
            float qv2 = __shfl_xor_sync(0xffffffffu, v2, off);
            int   qi1 = __shfl_xor_sync(0xffffffffu, i1, off);
            int   qi2 = __shfl_xor_sync(0xffffffffu, i2, off);
            bool pf = (v1 > qv1) || (v1 == qv1 && i1 < qi1);
            float cv = pf ? qv1 : v1;  int ci = pf ? qi1 : i1;   // loser of top
            float sv = pf ? v2  : qv2; int si = pf ? i2  : qi2;  // winner's second
            if (!pf) { v1 = qv1; i1 = qi1; }
            bool s2 = (sv > cv) || (sv == cv && si < ci);
            v2 = s2 ? sv : cv; i2 = s2 ? si : ci;
        }

        float inv = 1.f / sum;
        float p0 = e0 * inv, p1 = e1 * inv;
        *(float2*)&out[OFF_P + (size_t)t * NEXP + lane * 2] = make_float2(p0, p1);
        pimp0 += p0; pimp1 += p1;

        // probs at top indices: bit-identical to gathered values
        float pt1 = __expf(v1) * inv;
        float pt2 = __expf(v2) * inv;

        float s1 = (1.0f - pt1) + pt1;
        float s2v = (1.0f - pt2) + pt2;
        float dsum = fmaxf(s1 + s2v, 1e-9f);

        if (lane == 0) {
            out[OFF_IDX + t * 2]     = (float)i1;
            out[OFF_IDX + t * 2 + 1] = (float)i2;
            out[OFF_SC + t * 2]      = s1 / dsum;
            out[OFF_SC + t * 2 + 1]  = s2v / dsum;
            atomicAdd(&g_loadcnt[i1], 1);
            atomicAdd(&g_loadcnt[i2], 1);
        }
    }

    simp[warp * 64 + lane * 2]     = pimp0;
    simp[warp * 64 + lane * 2 + 1] = pimp1;
    __syncthreads();
    if (threadIdx.x < 64) {
        float a = 0.f;
        #pragma unroll
        for (int w = 0; w < 8; w++) a += simp[w * 64 + threadIdx.x];
        atomicAdd(&g_imp[threadIdx.x], a);
    }

    // last finished block writes importance / load outputs
    __syncthreads();
    if (threadIdx.x == 0) {
        __threadfence();
        is_last = (atomicAdd(&g_fincnt, 1) == (int)gridDim.x - 1);
    }
    __syncthreads();
    if (is_last && threadIdx.x < 64) {
        __threadfence();
        int e = threadIdx.x;
        out[OFF_IMP + e]  = g_imp[e] * (1.f / TOKENS);
        out[OFF_LOAD + e] = (float)g_loadcnt[e] * (1.f / TOKENS);
    }
}

// ---------------- launch ----------------
extern "C" void kernel_launch(void* const* d_in, const int* in_sizes, int n_in,
                              void* d_out, int out_size) {
    const float* x     = (const float*)d_in[0];
    const float* Wg    = (const float*)d_in[1];
    const float* gamma = (const float*)d_in[2];
    const float* beta  = (const float*)d_in[3];
    const float* W1    = (const float*)d_in[4];
    const float* W2    = (const float*)d_in[5];
    float* out = (float*)d_out;

    cudaFuncSetAttribute(gemm1_mma, cudaFuncAttributeMaxDynamicSharedMemorySize, G2_SMEM);
    cudaFuncSetAttribute(ln_logits, cudaFuncAttributeMaxDynamicSharedMemorySize, LN_SMEM);

    prep_kernel<<<8320, 256>>>(W1, Wg, gamma, beta);
    ln_logits<<<TOKENS / 64, 256, LN_SMEM>>>(x);
    dim3 g3(HDIM / G2_BN, TOKENS / 128);
    gemm1_mma<<<g3, 256, G2_SMEM>>>(x, W2);
    finalize_kernel<<<TOKENS / 32, 256>>>(out);
}

// round 15
// speedup vs baseline: 1.1008x; 1.0176x over previous
#include <cuda_runtime.h>
#include <cuda_bf16.h>
#include <math.h>
#include <stdint.h>

#define TOKENS 16384
#define DDIM   2048
#define NEXP   64
#define HDIM   1024

// Output layout (float32): idx [16384*2] | scores [16384*2] | probs [16384*64] | imp [64] | load [64]
#define OFF_IDX   0
#define OFF_SC    32768
#define OFF_P     65536
#define OFF_IMP   1114112
#define OFF_LOAD  1114176

// ---------------- scratch ----------------
__device__ __nv_bfloat16 g_w1[(size_t)HDIM * DDIM];        // W1 * gamma, bf16
__device__ __nv_bfloat16 g_wg_hi[(size_t)NEXP * DDIM];
__device__ __nv_bfloat16 g_wg_lo[(size_t)NEXP * DDIM];
__device__ float g_logits[(size_t)TOKENS * NEXP];
__device__ float g_diffpre[TOKENS];
__device__ float g_mu[TOKENS];
__device__ float g_rstd[TOKENS];
__device__ float g_c1[HDIM];
__device__ float g_c2[HDIM];
__device__ float g_imp[NEXP];
__device__ int   g_loadcnt[NEXP];
__device__ int   g_bmcnt[TOKENS / 128];
__device__ int   g_fincnt;

// ---------------- shared helpers ----------------
__device__ __forceinline__ uint32_t smem_u32(const void* p) {
    uint32_t a;
    asm("{ .reg .u64 t; cvta.to.shared.u64 t, %1; cvt.u32.u64 %0, t; }" : "=r"(a) : "l"(p));
    return a;
}
__device__ __forceinline__ uint32_t g1_sw(uint32_t r, uint32_t c) {
    return r * 64 + ((c ^ ((r >> 1) & 3)) * 16);
}
__device__ __forceinline__ void ldsm_x4(uint32_t& r0, uint32_t& r1, uint32_t& r2, uint32_t& r3,
                                        uint32_t addr) {
    asm volatile("ldmatrix.sync.aligned.m8n8.x4.shared.b16 {%0,%1,%2,%3}, [%4];"
                 : "=r"(r0), "=r"(r1), "=r"(r2), "=r"(r3) : "r"(addr));
}
__device__ __forceinline__ float gelu_exact(float v) {
    return 0.5f * v * (1.0f + erff(v * 0.70710678118654752440f));
}
#define MMA_BF16(acc, a, b0, b1) \
    asm volatile( \
        "mma.sync.aligned.m16n8k16.row.col.f32.bf16.bf16.f32 " \
        "{%0,%1,%2,%3}, {%4,%5,%6,%7}, {%8,%9}, {%0,%1,%2,%3};\n" \
        : "+f"((acc)[0]), "+f"((acc)[1]), "+f"((acc)[2]), "+f"((acc)[3]) \
        : "r"((a)[0]), "r"((a)[1]), "r"((a)[2]), "r"((a)[3]), "r"(b0), "r"(b1))

// =========================================================================
// prep: W1*gamma -> bf16, Wg hi/lo, zeros, C1/C2.  grid 8192 + 128
// =========================================================================
__global__ __launch_bounds__(256)
void prep_kernel(const float* __restrict__ W1, const float* __restrict__ Wg,
                 const float* __restrict__ gamma, const float* __restrict__ beta) {
    int b = blockIdx.x;
    int tid = threadIdx.x;
    if (b < 8192) {
        int i = b * 256 + tid;
        g_w1[i] = __float2bfloat16(W1[i] * gamma[i & (DDIM - 1)]);
        if (i < NEXP * DDIM) {
            float v = Wg[i];
            __nv_bfloat16 hi = __float2bfloat16(v);
            g_wg_hi[i] = hi;
            g_wg_lo[i] = __float2bfloat16(v - __bfloat162float(hi));
        }
        if (i < TOKENS) g_diffpre[i] = 0.f;
        if (i < NEXP) { g_loadcnt[i] = 0; g_imp[i] = 0.f; }
        if (i < TOKENS / 128) g_bmcnt[i] = 0;
        if (i == 0) g_fincnt = 0;
    } else {
        int n = (b - 8192) * 8 + (tid >> 5);
        int lane = tid & 31;
        const float* wr = W1 + (size_t)n * DDIM;
        float c1 = 0.f, c2 = 0.f;
        #pragma unroll 8
        for (int k = 0; k < 64; k++) {
            int d = lane + k * 32;
            float w = wr[d];
            c1 += w * gamma[d];
            c2 += w * beta[d];
        }
        #pragma unroll
        for (int off = 16; off; off >>= 1) {
            c1 += __shfl_xor_sync(0xffffffffu, c1, off);
            c2 += __shfl_xor_sync(0xffffffffu, c2, off);
        }
        if (lane == 0) { g_c1[n] = c1; g_c2[n] = c2; }
    }
}

// =========================================================================
// ln_logits (R14): 64-token tiles, 256 threads, 2 CTAs/SM.
// =========================================================================
#define LN_STG_B 16384
#define LN_SMEM  (2 * LN_STG_B + 2048)

__global__ __launch_bounds__(256, 2)
void ln_logits(const float* __restrict__ x) {
    extern __shared__ __align__(128) char lsm[];
    uint32_t sb = smem_u32(lsm);
    float* sS = (float*)(lsm + 2 * LN_STG_B);
    float* sQ = sS + 256;

    int tile = blockIdx.x;
    int tid = threadIdx.x;
    int warp = tid >> 5, lane = tid & 31;
    const float* xb = x + (size_t)tile * 64 * DDIM;

    int r0 = tid >> 2;
    int q  = tid & 3;
    int wr = tid >> 2;
    int wc = tid & 3;
    int wm  = (warp & 3) * 16;
    int wn2 = (warp >> 2) * 32;
    int lrow = lane & 15;
    int lsel = lane >> 4;

    float s = 0.f, qq = 0.f;
    float acc[4][4];
    #pragma unroll
    for (int j = 0; j < 4; j++)
        #pragma unroll
        for (int r = 0; r < 4; r++) acc[j][r] = 0.f;

    float4 v0 = *(const float4*)&xb[(size_t)r0 * DDIM + q * 8];
    float4 v1 = *(const float4*)&xb[(size_t)r0 * DDIM + q * 8 + 4];
    uint4 wvh = *(const uint4*)&g_wg_hi[(size_t)wr * DDIM + wc * 8];
    uint4 wvl = *(const uint4*)&g_wg_lo[(size_t)wr * DDIM + wc * 8];

    {
        uint32_t ao = g1_sw((uint32_t)r0, (uint32_t)q);
        s += v0.x + v0.y + v0.z + v0.w + v1.x + v1.y + v1.z + v1.w;
        qq += v0.x*v0.x + v0.y*v0.y + v0.z*v0.z + v0.w*v0.w
            + v1.x*v1.x + v1.y*v1.y + v1.z*v1.z + v1.w*v1.w;
        __align__(16) __nv_bfloat16 hb[8], lb[8];
        float vv[8] = {v0.x, v0.y, v0.z, v0.w, v1.x, v1.y, v1.z, v1.w};
        #pragma unroll
        for (int i = 0; i < 8; i++) {
            __nv_bfloat16 b = __float2bfloat16(vv[i]);
            hb[i] = b;
            lb[i] = __float2bfloat16(vv[i] - __bfloat162float(b));
        }
        *(uint4*)(lsm + ao) = *(uint4*)hb;
        *(uint4*)(lsm + 4096 + ao) = *(uint4*)lb;
        uint32_t wo = g1_sw((uint32_t)wr, (uint32_t)wc);
        *(uint4*)(lsm + 8192 + wo) = wvh;
        *(uint4*)(lsm + 12288 + wo) = wvl;
    }
    __syncthreads();

    #pragma unroll 2
    for (int kc = 0; kc < 64; kc++) {
        if (kc < 63) {
            int k0n = (kc + 1) * 32;
            v0 = *(const float4*)&xb[(size_t)r0 * DDIM + k0n + q * 8];
            v1 = *(const float4*)&xb[(size_t)r0 * DDIM + k0n + q * 8 + 4];
            wvh = *(const uint4*)&g_wg_hi[(size_t)wr * DDIM + k0n + wc * 8];
            wvl = *(const uint4*)&g_wg_lo[(size_t)wr * DDIM + k0n + wc * 8];
        }

        {
            uint32_t st = sb + (kc & 1) * LN_STG_B;
            #pragma unroll
            for (int ks = 0; ks < 2; ks++) {
                uint32_t ao = g1_sw((uint32_t)(wm + lrow), (uint32_t)(ks * 2 + lsel));
                uint32_t ah[4], al[4];
                ldsm_x4(ah[0], ah[1], ah[2], ah[3], st + ao);
                ldsm_x4(al[0], al[1], al[2], al[3], st + 4096 + ao);
                uint32_t bh[4][2], bl[4][2];
                #pragma unroll
                for (int jb = 0; jb < 2; jb++) {
                    uint32_t wo = g1_sw((uint32_t)(wn2 + jb * 16 + lrow),
                                        (uint32_t)(ks * 2 + lsel));
                    uint32_t t0, t1, t2, t3;
                    ldsm_x4(t0, t1, t2, t3, st + 8192 + wo);
                    bh[jb * 2][0] = t0;     bh[jb * 2][1] = t2;
                    bh[jb * 2 + 1][0] = t1; bh[jb * 2 + 1][1] = t3;
                    ldsm_x4(t0, t1, t2, t3, st + 12288 + wo);
                    bl[jb * 2][0] = t0;     bl[jb * 2][1] = t2;
                    bl[jb * 2 + 1][0] = t1; bl[jb * 2 + 1][1] = t3;
                }
                #pragma unroll
                for (int j = 0; j < 4; j++) {
                    MMA_BF16(acc[j], ah, bh[j][0], bh[j][1]);
                    MMA_BF16(acc[j], ah, bl[j][0], bl[j][1]);
                    MMA_BF16(acc[j], al, bh[j][0], bh[j][1]);
                }
            }
        }

        if (kc < 63) {
            char* stn = lsm + ((kc + 1) & 1) * LN_STG_B;
            uint32_t ao = g1_sw((uint32_t)r0, (uint32_t)q);
            s += v0.x + v0.y + v0.z + v0.w + v1.x + v1.y + v1.z + v1.w;
            qq += v0.x*v0.x + v0.y*v0.y + v0.z*v0.z + v0.w*v0.w
                + v1.x*v1.x + v1.y*v1.y + v1.z*v1.z + v1.w*v1.w;
            __align__(16) __nv_bfloat16 hb[8], lb[8];
            float vv[8] = {v0.x, v0.y, v0.z, v0.w, v1.x, v1.y, v1.z, v1.w};
            #pragma unroll
            for (int i = 0; i < 8; i++) {
                __nv_bfloat16 b = __float2bfloat16(vv[i]);
                hb[i] = b;
                lb[i] = __float2bfloat16(vv[i] - __bfloat162float(b));
            }
            *(uint4*)(stn + ao) = *(uint4*)hb;
            *(uint4*)(stn + 4096 + ao) = *(uint4*)lb;
            uint32_t wo = g1_sw((uint32_t)wr, (uint32_t)wc);
            *(uint4*)(stn + 8192 + wo) = wvh;
            *(uint4*)(stn + 12288 + wo) = wvl;
        }
        __syncthreads();
    }

    sS[r0 * 4 + q] = s;
    sQ[r0 * 4 + q] = qq;
    __syncthreads();
    if (tid < 64) {
        float ts = sS[tid*4] + sS[tid*4+1] + sS[tid*4+2] + sS[tid*4+3];
        float tq = sQ[tid*4] + sQ[tid*4+1] + sQ[tid*4+2] + sQ[tid*4+3];
        float mean = ts * (1.f / DDIM);
        float var  = tq * (1.f / DDIM) - mean * mean;
        g_mu[tile * 64 + tid]   = mean;
        g_rstd[tile * 64 + tid] = rsqrtf(var + 1e-5f);
    }

    #pragma unroll
    for (int j = 0; j < 4; j++) {
        int row = tile * 64 + wm + (lane >> 2);
        int col = wn2 + j * 8 + (lane & 3) * 2;
        float2 c01; c01.x = acc[j][0]; c01.y = acc[j][1];
        float2 c23; c23.x = acc[j][2]; c23.y = acc[j][3];
        *(float2*)&g_logits[(size_t)row * NEXP + col] = c01;
        *(float2*)&g_logits[(size_t)(row + 8) * NEXP + col] = c23;
    }
}

// =========================================================================
// gemm1 + inline per-bm finalize (last bn-CTA of each bm runs it).
// =========================================================================
#define G2_STAGES 3
#define G2_BK     32
#define G2_BN     256
#define G2_BBYTES 16384
#define G2_ABYTES 8192
#define G2_A_OFF  (G2_STAGES * G2_BBYTES)
#define G2_SMEM   (G2_A_OFF + 2 * G2_ABYTES)
#define G2_CHUNKS (DDIM / G2_BK)

__device__ __forceinline__ void g2_stage_B(uint32_t sB, const __nv_bfloat16* Bg,
                                           int k0, int tid) {
    #pragma unroll
    for (int i = 0; i < 4; i++) {
        int idx = tid + i * 256;
        int r = idx >> 2, c = idx & 3;
        uint32_t dst = sB + g1_sw(r, c);
        asm volatile("cp.async.cg.shared.global [%0], [%1], 16;\n"
                     :: "r"(dst), "l"(Bg + (size_t)r * DDIM + k0 + c * 8));
    }
    asm volatile("cp.async.commit_group;\n");
}

__global__ __launch_bounds__(256, 1)
void gemm1_mma(const float* __restrict__ x, const float* __restrict__ W2,
               float* __restrict__ out) {
    extern __shared__ __align__(128) char g1sm[];
    uint32_t sb = smem_u32(g1sm);
    int tid = threadIdx.x;
    int warp = tid >> 5, lane = tid & 31;
    int bn = blockIdx.x, bm = blockIdx.y;
    int wm = (warp & 1) * 64;
    int wn = (warp >> 1) * 64;

    const float* xb = x + (size_t)(bm * 128) * DDIM;
    const __nv_bfloat16* Bg = g_w1 + (size_t)(bn * G2_BN) * DDIM;

    int r0 = tid >> 1;
    int hsel = tid & 1;
    int lrow = lane & 15;
    int lsel = lane >> 4;

    float acc[4][8][4];
    #pragma unroll
    for (int i = 0; i < 4; i++)
        #pragma unroll
        for (int j = 0; j < 8; j++)
            #pragma unroll
            for (int r = 0; r < 4; r++) acc[i][j][r] = 0.f;

    g2_stage_B(sb + 0 * G2_BBYTES, Bg, 0, tid);
    g2_stage_B(sb + 1 * G2_BBYTES, Bg, G2_BK, tid);
    float4 xv[4];
    #pragma unroll
    for (int i = 0; i < 4; i++)
        xv[i] = *(const float4*)&xb[(size_t)r0 * DDIM + hsel * 16 + i * 4];

    #pragma unroll 1
    for (int c = 0; c < G2_CHUNKS; c++) {
        if (c + 2 < G2_CHUNKS)
            g2_stage_B(sb + ((c + 2) % G2_STAGES) * G2_BBYTES, Bg, (c + 2) * G2_BK, tid);

        {
            uint32_t sA = sb + G2_A_OFF + (c & 1) * G2_ABYTES;
            __align__(16) __nv_bfloat16 ob[16];
            #pragma unroll
            for (int i = 0; i < 4; i++) {
                __nv_bfloat162 p0 = __floats2bfloat162_rn(xv[i].x, xv[i].y);
                __nv_bfloat162 p1 = __floats2bfloat162_rn(xv[i].z, xv[i].w);
                *(uint32_t*)&ob[i * 4]     = *(uint32_t*)&p0;
                *(uint32_t*)&ob[i * 4 + 2] = *(uint32_t*)&p1;
            }
            #pragma unroll
            for (int j = 0; j < 2; j++) {
                uint32_t dst = sA + g1_sw((uint32_t)r0, (uint32_t)(hsel * 2 + j));
                *(uint4*)(g1sm + (dst - sb)) = *(uint4*)&ob[j * 8];
            }
        }

        if (c + 1 < G2_CHUNKS) {
            #pragma unroll
            for (int i = 0; i < 4; i++)
                xv[i] = *(const float4*)&xb[(size_t)r0 * DDIM + (c + 1) * G2_BK + hsel * 16 + i * 4];
        }

        if (c + 2 < G2_CHUNKS) {
            asm volatile("cp.async.wait_group 2;\n");
        } else if (c + 2 == G2_CHUNKS) {
            asm volatile("cp.async.wait_group 1;\n");
        } else {
            asm volatile("cp.async.wait_group 0;\n");
        }
        __syncthreads();

        uint32_t sA = sb + G2_A_OFF + (c & 1) * G2_ABYTES;
        uint32_t sB = sb + (c % G2_STAGES) * G2_BBYTES;

        #pragma unroll
        for (int ks = 0; ks < 2; ks++) {
            uint32_t af[4][4], bf[8][2];
            #pragma unroll
            for (int i = 0; i < 4; i++) {
                uint32_t r = (uint32_t)(wm + i * 16 + lrow);
                ldsm_x4(af[i][0], af[i][1], af[i][2], af[i][3],
                        sA + g1_sw(r, (uint32_t)(ks * 2 + lsel)));
            }
            #pragma unroll
            for (int jb = 0; jb < 4; jb++) {
                uint32_t r = (uint32_t)(wn + jb * 16 + lrow);
                uint32_t q0, q1, q2, q3;
                ldsm_x4(q0, q1, q2, q3, sB + g1_sw(r, (uint32_t)(ks * 2 + lsel)));
                bf[jb * 2][0] = q0;     bf[jb * 2][1] = q2;
                bf[jb * 2 + 1][0] = q1; bf[jb * 2 + 1][1] = q3;
            }
            #pragma unroll
            for (int i = 0; i < 4; i++)
                #pragma unroll
                for (int j = 0; j < 8; j++)
                    MMA_BF16(acc[i][j], af[i], bf[j][0], bf[j][1]);
        }
        __syncthreads();
    }

    // epilogue: h1 = rs*acc - rs*mu*C1 + C2; gelu*W2; reduce
    float part0[4] = {0.f, 0.f, 0.f, 0.f};
    float part1[4] = {0.f, 0.f, 0.f, 0.f};
    float rs0[4], rm0[4], rs1[4], rm1[4];
    #pragma unroll
    for (int i = 0; i < 4; i++) {
        int m0 = bm * 128 + wm + i * 16 + (lane >> 2);
        rs0[i] = g_rstd[m0];     rm0[i] = rs0[i] * g_mu[m0];
        rs1[i] = g_rstd[m0 + 8]; rm1[i] = rs1[i] * g_mu[m0 + 8];
    }
    #pragma unroll
    for (int j = 0; j < 8; j++) {
        int n = bn * G2_BN + wn + j * 8 + (lane & 3) * 2;
        float2 c1 = *(const float2*)&g_c1[n];
        float2 c2 = *(const float2*)&g_c2[n];
        float2 w2 = *(const float2*)&W2[n];
        #pragma unroll
        for (int i = 0; i < 4; i++) {
            float h00 = rs0[i] * acc[i][j][0] - rm0[i] * c1.x + c2.x;
            float h01 = rs0[i] * acc[i][j][1] - rm0[i] * c1.y + c2.y;
            float h10 = rs1[i] * acc[i][j][2] - rm1[i] * c1.x + c2.x;
            float h11 = rs1[i] * acc[i][j][3] - rm1[i] * c1.y + c2.y;
            part0[i] += gelu_exact(h00) * w2.x + gelu_exact(h01) * w2.y;
            part1[i] += gelu_exact(h10) * w2.x + gelu_exact(h11) * w2.y;
        }
    }
    #pragma unroll
    for (int i = 0; i < 4; i++) {
        part0[i] += __shfl_xor_sync(0xffffffffu, part0[i], 1);
        part0[i] += __shfl_xor_sync(0xffffffffu, part0[i], 2);
        part1[i] += __shfl_xor_sync(0xffffffffu, part1[i], 1);
        part1[i] += __shfl_xor_sync(0xffffffffu, part1[i], 2);
    }
    if ((lane & 3) == 0) {
        int mbase = bm * 128 + wm + (lane >> 2);
        #pragma unroll
        for (int i = 0; i < 4; i++) {
            atomicAdd(&g_diffpre[mbase + i * 16], part0[i]);
            atomicAdd(&g_diffpre[mbase + i * 16 + 8], part1[i]);
        }
    }

    // ---- last bn-CTA of this bm: inline finalize for tokens [bm*128, +128) ----
    __shared__ int slast;
    __threadfence();
    __syncthreads();
    if (tid == 0) slast = (atomicAdd(&g_bmcnt[bm], 1) == 3);
    __syncthreads();
    if (!slast) return;

    float* simp = (float*)g1sm;   // 8*64 floats
    {
        // prefetch 16 tokens' logits + diffpre (warp-owned rows)
        float2 lgv[16]; float dpv[16];
        int t0 = bm * 128 + warp * 16;
        #pragma unroll
        for (int k = 0; k < 16; k++) {
            lgv[k] = *(const float2*)&g_logits[(size_t)(t0 + k) * NEXP + lane * 2];
            dpv[k] = g_diffpre[t0 + k];
        }

        float pimp0 = 0.f, pimp1 = 0.f;
        #pragma unroll
        for (int k = 0; k < 16; k++) {
            int t = t0 + k;
            float diff = 1.f / (1.f + __expf(-dpv[k]));
            float rden = 1.f / (1.f + diff);
            float l0 = lgv[k].x * rden;
            float l1 = lgv[k].y * rden;

            float e0 = __expf(l0), e1 = __expf(l1);
            float sum = e0 + e1;

            float v1, v2; int i1, i2;
            if (l1 > l0) { v1 = l1; i1 = lane * 2 + 1; v2 = l0; i2 = lane * 2; }
            else         { v1 = l0; i1 = lane * 2;     v2 = l1; i2 = lane * 2 + 1; }

            #pragma unroll
            for (int off = 16; off; off >>= 1) {
                sum += __shfl_xor_sync(0xffffffffu, sum, off);
                float qv1 = __shfl_xor_sync(0xffffffffu, v1, off);
                float qv2 = __shfl_xor_sync(0xffffffffu, v2, off);
                int   qi1 = __shfl_xor_sync(0xffffffffu, i1, off);
                int   qi2 = __shfl_xor_sync(0xffffffffu, i2, off);
                bool pf = (v1 > qv1) || (v1 == qv1 && i1 < qi1);
                float cv = pf ? qv1 : v1;  int ci = pf ? qi1 : i1;
                float sv = pf ? v2  : qv2; int si = pf ? i2  : qi2;
                if (!pf) { v1 = qv1; i1 = qi1; }
                bool s2 = (sv > cv) || (sv == cv && si < ci);
                v2 = s2 ? sv : cv; i2 = s2 ? si : ci;
            }

            float inv = 1.f / sum;
            float p0 = e0 * inv, p1 = e1 * inv;
            *(float2*)&out[OFF_P + (size_t)t * NEXP + lane * 2] = make_float2(p0, p1);
            pimp0 += p0; pimp1 += p1;

            float pt1 = __expf(v1) * inv;
            float pt2 = __expf(v2) * inv;
            float s1 = (1.0f - pt1) + pt1;
            float s2v = (1.0f - pt2) + pt2;
            float dsum = fmaxf(s1 + s2v, 1e-9f);

            if (lane == 0) {
                out[OFF_IDX + t * 2]     = (float)i1;
                out[OFF_IDX + t * 2 + 1] = (float)i2;
                out[OFF_SC + t * 2]      = s1 / dsum;
                out[OFF_SC + t * 2 + 1]  = s2v / dsum;
                atomicAdd(&g_loadcnt[i1], 1);
                atomicAdd(&g_loadcnt[i2], 1);
            }
        }

        simp[warp * 64 + lane * 2]     = pimp0;
        simp[warp * 64 + lane * 2 + 1] = pimp1;
    }
    __syncthreads();
    if (tid < 64) {
        float a = 0.f;
        #pragma unroll
        for (int w = 0; w < 8; w++) a += simp[w * 64 + tid];
        atomicAdd(&g_imp[tid], a);
    }

    // global-last finalizer writes importance / load
    __shared__ int slast2;
    __threadfence();
    __syncthreads();
    if (tid == 0) slast2 = (atomicAdd(&g_fincnt, 1) == TOKENS / 128 - 1);
    __syncthreads();
    if (slast2 && tid < 64) {
        __threadfence();
        out[OFF_IMP + tid]  = g_imp[tid] * (1.f / TOKENS);
        out[OFF_LOAD + tid] = (float)g_loadcnt[tid] * (1.f / TOKENS);
    }
}

// ---------------- launch ----------------
extern "C" void kernel_launch(void* const* d_in, const int* in_sizes, int n_in,
                              void* d_out, int out_size) {
    const float* x     = (const float*)d_in[0];
    const float* Wg    = (const float*)d_in[1];
    const float* gamma = (const float*)d_in[2];
    const float* beta  = (const float*)d_in[3];
    const float* W1    = (const float*)d_in[4];
    const float* W2    = (const float*)d_in[5];
    float* out = (float*)d_out;

    cudaFuncSetAttribute(gemm1_mma, cudaFuncAttributeMaxDynamicSharedMemorySize, G2_SMEM);
    cudaFuncSetAttribute(ln_logits, cudaFuncAttributeMaxDynamicSharedMemorySize, LN_SMEM);

    prep_kernel<<<8320, 256>>>(W1, Wg, gamma, beta);
    ln_logits<<<TOKENS / 64, 256, LN_SMEM>>>(x);
    dim3 g3(HDIM / G2_BN, TOKENS / 128);
    gemm1_mma<<<g3, 256, G2_SMEM>>>(x, W2, out);
}

// round 17
// speedup vs baseline: 1.1295x; 1.0261x over previous
#include <cuda_runtime.h>
#include <cuda_bf16.h>
#include <math.h>
#include <stdint.h>

#define TOKENS 16384
#define DDIM   2048
#define NEXP   64
#define HDIM   1024

// Output layout (float32): idx [16384*2] | scores [16384*2] | probs [16384*64] | imp [64] | load [64]
#define OFF_IDX   0
#define OFF_SC    32768
#define OFF_P     65536
#define OFF_IMP   1114112
#define OFF_LOAD  1114176

// ---------------- scratch ----------------
__device__ __nv_bfloat16 g_w1[(size_t)HDIM * DDIM];        // W1 * gamma, bf16
__device__ __nv_bfloat16 g_wg_hi[(size_t)NEXP * DDIM];
__device__ __nv_bfloat16 g_wg_lo[(size_t)NEXP * DDIM];
__device__ float g_logits[(size_t)TOKENS * NEXP];
__device__ float g_diffpre[TOKENS];
__device__ float g_mu[TOKENS];
__device__ float g_rstd[TOKENS];
__device__ float g_c1[HDIM];
__device__ float g_c2[HDIM];
__device__ float g_imp[NEXP];
__device__ int   g_loadcnt[NEXP];
__device__ int   g_bmcnt[TOKENS / 128];
__device__ int   g_fincnt;

// ---------------- shared helpers ----------------
__device__ __forceinline__ uint32_t smem_u32(const void* p) {
    uint32_t a;
    asm("{ .reg .u64 t; cvta.to.shared.u64 t, %1; cvt.u32.u64 %0, t; }" : "=r"(a) : "l"(p));
    return a;
}
__device__ __forceinline__ uint32_t g1_sw(uint32_t r, uint32_t c) {
    return r * 64 + ((c ^ ((r >> 1) & 3)) * 16);
}
__device__ __forceinline__ void ldsm_x4(uint32_t& r0, uint32_t& r1, uint32_t& r2, uint32_t& r3,
                                        uint32_t addr) {
    asm volatile("ldmatrix.sync.aligned.m8n8.x4.shared.b16 {%0,%1,%2,%3}, [%4];"
                 : "=r"(r0), "=r"(r1), "=r"(r2), "=r"(r3) : "r"(addr));
}
__device__ __forceinline__ float gelu_exact(float v) {
    return 0.5f * v * (1.0f + erff(v * 0.70710678118654752440f));
}
#define MMA_BF16(acc, a, b0, b1) \
    asm volatile( \
        "mma.sync.aligned.m16n8k16.row.col.f32.bf16.bf16.f32 " \
        "{%0,%1,%2,%3}, {%4,%5,%6,%7}, {%8,%9}, {%0,%1,%2,%3};\n" \
        : "+f"((acc)[0]), "+f"((acc)[1]), "+f"((acc)[2]), "+f"((acc)[3]) \
        : "r"((a)[0]), "r"((a)[1]), "r"((a)[2]), "r"((a)[3]), "r"(b0), "r"(b1))

// =========================================================================
// prep: Wg hi/lo conversion + zeros only. grid 512.
// =========================================================================
__global__ __launch_bounds__(256)
void prep_kernel(const float* __restrict__ Wg) {
    int i = blockIdx.x * 256 + threadIdx.x;
    float v = Wg[i];
    __nv_bfloat16 hi = __float2bfloat16(v);
    g_wg_hi[i] = hi;
    g_wg_lo[i] = __float2bfloat16(v - __bfloat162float(hi));
    if (i < TOKENS) g_diffpre[i] = 0.f;
    if (i < NEXP) { g_loadcnt[i] = 0; g_imp[i] = 0.f; }
    if (i < TOKENS / 128) g_bmcnt[i] = 0;
    if (i == 0) g_fincnt = 0;
}

// =========================================================================
// ln_logits merged kernel, grid 512:
//   b <  256: LN stats + base-logits GEMM tile (64 tokens, 2 CTAs/SM)
//   b <  384: W1*gamma -> bf16 conversion slice (16384 elems each)
//   b >= 384: C1/C2 rows (8 each)
// =========================================================================
#define LN_STG_B 16384
#define LN_SMEM  (2 * LN_STG_B + 2048)

__global__ __launch_bounds__(256, 2)
void ln_logits(const float* __restrict__ x, const float* __restrict__ W1,
               const float* __restrict__ gamma, const float* __restrict__ beta) {
    int bid = blockIdx.x;
    int tid = threadIdx.x;

    if (bid >= 384) {
        // ---- C1/C2 ----
        int n = (bid - 384) * 8 + (tid >> 5);
        int lane = tid & 31;
        const float* wrow = W1 + (size_t)n * DDIM;
        float c1 = 0.f, c2 = 0.f;
        #pragma unroll 8
        for (int k = 0; k < 64; k++) {
            int d = lane + k * 32;
            float w = wrow[d];
            c1 += w * gamma[d];
            c2 += w * beta[d];
        }
        #pragma unroll
        for (int off = 16; off; off >>= 1) {
            c1 += __shfl_xor_sync(0xffffffffu, c1, off);
            c2 += __shfl_xor_sync(0xffffffffu, c2, off);
        }
        if (lane == 0) { g_c1[n] = c1; g_c2[n] = c2; }
        return;
    }
    if (bid >= 256) {
        // ---- W1 * gamma -> bf16  (HDIM*DDIM / 128 CTAs = 16384 elems each) ----
        size_t base = (size_t)(bid - 256) * 16384;
        #pragma unroll 4
        for (int it = 0; it < 64; it++) {
            size_t i = base + (size_t)it * 256 + tid;
            g_w1[i] = __float2bfloat16(W1[i] * gamma[i & (DDIM - 1)]);
        }
        return;
    }

    // ---- LN + logits tile ----
    extern __shared__ __align__(128) char lsm[];
    uint32_t sb = smem_u32(lsm);
    float* sS = (float*)(lsm + 2 * LN_STG_B);
    float* sQ = sS + 256;

    int tile = bid;
    int warp = tid >> 5, lane = tid & 31;
    const float* xb = x + (size_t)tile * 64 * DDIM;

    int r0 = tid >> 2;
    int q  = tid & 3;
    int wr = tid >> 2;
    int wc = tid & 3;
    int wm  = (warp & 3) * 16;
    int wn2 = (warp >> 2) * 32;
    int lrow = lane & 15;
    int lsel = lane >> 4;

    float s = 0.f, qq = 0.f;
    float acc[4][4];
    #pragma unroll
    for (int j = 0; j < 4; j++)
        #pragma unroll
        for (int r = 0; r < 4; r++) acc[j][r] = 0.f;

    float4 v0 = *(const float4*)&xb[(size_t)r0 * DDIM + q * 8];
    float4 v1 = *(const float4*)&xb[(size_t)r0 * DDIM + q * 8 + 4];
    uint4 wvh = *(const uint4*)&g_wg_hi[(size_t)wr * DDIM + wc * 8];
    uint4 wvl = *(const uint4*)&g_wg_lo[(size_t)wr * DDIM + wc * 8];

    {
        uint32_t ao = g1_sw((uint32_t)r0, (uint32_t)q);
        s += v0.x + v0.y + v0.z + v0.w + v1.x + v1.y + v1.z + v1.w;
        qq += v0.x*v0.x + v0.y*v0.y + v0.z*v0.z + v0.w*v0.w
            + v1.x*v1.x + v1.y*v1.y + v1.z*v1.z + v1.w*v1.w;
        __align__(16) __nv_bfloat16 hb[8], lb[8];
        float vv[8] = {v0.x, v0.y, v0.z, v0.w, v1.x, v1.y, v1.z, v1.w};
        #pragma unroll
        for (int i = 0; i < 8; i++) {
            __nv_bfloat16 b = __float2bfloat16(vv[i]);
            hb[i] = b;
            lb[i] = __float2bfloat16(vv[i] - __bfloat162float(b));
        }
        *(uint4*)(lsm + ao) = *(uint4*)hb;
        *(uint4*)(lsm + 4096 + ao) = *(uint4*)lb;
        uint32_t wo = g1_sw((uint32_t)wr, (uint32_t)wc);
        *(uint4*)(lsm + 8192 + wo) = wvh;
        *(uint4*)(lsm + 12288 + wo) = wvl;
    }
    __syncthreads();

    #pragma unroll 2
    for (int kc = 0; kc < 64; kc++) {
        if (kc < 63) {
            int k0n = (kc + 1) * 32;
            v0 = *(const float4*)&xb[(size_t)r0 * DDIM + k0n + q * 8];
            v1 = *(const float4*)&xb[(size_t)r0 * DDIM + k0n + q * 8 + 4];
            wvh = *(const uint4*)&g_wg_hi[(size_t)wr * DDIM + k0n + wc * 8];
            wvl = *(const uint4*)&g_wg_lo[(size_t)wr * DDIM + k0n + wc * 8];
        }

        {
            uint32_t st = sb + (kc & 1) * LN_STG_B;
            #pragma unroll
            for (int ks = 0; ks < 2; ks++) {
                uint32_t ao = g1_sw((uint32_t)(wm + lrow), (uint32_t)(ks * 2 + lsel));
                uint32_t ah[4], al[4];
                ldsm_x4(ah[0], ah[1], ah[2], ah[3], st + ao);
                ldsm_x4(al[0], al[1], al[2], al[3], st + 4096 + ao);
                uint32_t bh[4][2], bl[4][2];
                #pragma unroll
                for (int jb = 0; jb < 2; jb++) {
                    uint32_t wo = g1_sw((uint32_t)(wn2 + jb * 16 + lrow),
                                        (uint32_t)(ks * 2 + lsel));
                    uint32_t t0, t1, t2, t3;
                    ldsm_x4(t0, t1, t2, t3, st + 8192 + wo);
                    bh[jb * 2][0] = t0;     bh[jb * 2][1] = t2;
                    bh[jb * 2 + 1][0] = t1; bh[jb * 2 + 1][1] = t3;
                    ldsm_x4(t0, t1, t2, t3, st + 12288 + wo);
                    bl[jb * 2][0] = t0;     bl[jb * 2][1] = t2;
                    bl[jb * 2 + 1][0] = t1; bl[jb * 2 + 1][1] = t3;
                }
                #pragma unroll
                for (int j = 0; j < 4; j++) {
                    MMA_BF16(acc[j], ah, bh[j][0], bh[j][1]);
                    MMA_BF16(acc[j], ah, bl[j][0], bl[j][1]);
                    MMA_BF16(acc[j], al, bh[j][0], bh[j][1]);
                }
            }
        }

        if (kc < 63) {
            char* stn = lsm + ((kc + 1) & 1) * LN_STG_B;
            uint32_t ao = g1_sw((uint32_t)r0, (uint32_t)q);
            s += v0.x + v0.y + v0.z + v0.w + v1.x + v1.y + v1.z + v1.w;
            qq += v0.x*v0.x + v0.y*v0.y + v0.z*v0.z + v0.w*v0.w
                + v1.x*v1.x + v1.y*v1.y + v1.z*v1.z + v1.w*v1.w;
            __align__(16) __nv_bfloat16 hb[8], lb[8];
            float vv[8] = {v0.x, v0.y, v0.z, v0.w, v1.x, v1.y, v1.z, v1.w};
            #pragma unroll
            for (int i = 0; i < 8; i++) {
                __nv_bfloat16 b = __float2bfloat16(vv[i]);
                hb[i] = b;
                lb[i] = __float2bfloat16(vv[i] - __bfloat162float(b));
            }
            *(uint4*)(stn + ao) = *(uint4*)hb;
            *(uint4*)(stn + 4096 + ao) = *(uint4*)lb;
            uint32_t wo = g1_sw((uint32_t)wr, (uint32_t)wc);
            *(uint4*)(stn + 8192 + wo) = wvh;
            *(uint4*)(stn + 12288 + wo) = wvl;
        }
        __syncthreads();
    }

    sS[r0 * 4 + q] = s;
    sQ[r0 * 4 + q] = qq;
    __syncthreads();
    if (tid < 64) {
        float ts = sS[tid*4] + sS[tid*4+1] + sS[tid*4+2] + sS[tid*4+3];
        float tq = sQ[tid*4] + sQ[tid*4+1] + sQ[tid*4+2] + sQ[tid*4+3];
        float mean = ts * (1.f / DDIM);
        float var  = tq * (1.f / DDIM) - mean * mean;
        g_mu[tile * 64 + tid]   = mean;
        g_rstd[tile * 64 + tid] = rsqrtf(var + 1e-5f);
    }

    #pragma unroll
    for (int j = 0; j < 4; j++) {
        int row = tile * 64 + wm + (lane >> 2);
        int col = wn2 + j * 8 + (lane & 3) * 2;
        float2 c01; c01.x = acc[j][0]; c01.y = acc[j][1];
        float2 c23; c23.x = acc[j][2]; c23.y = acc[j][3];
        *(float2*)&g_logits[(size_t)row * NEXP + col] = c01;
        *(float2*)&g_logits[(size_t)(row + 8) * NEXP + col] = c23;
    }
}

// =========================================================================
// gemm1 + inline per-bm finalize (R15, unchanged).
// =========================================================================
#define G2_STAGES 3
#define G2_BK     32
#define G2_BN     256
#define G2_BBYTES 16384
#define G2_ABYTES 8192
#define G2_A_OFF  (G2_STAGES * G2_BBYTES)
#define G2_SMEM   (G2_A_OFF + 2 * G2_ABYTES)
#define G2_CHUNKS (DDIM / G2_BK)

__device__ __forceinline__ void g2_stage_B(uint32_t sB, const __nv_bfloat16* Bg,
                                           int k0, int tid) {
    #pragma unroll
    for (int i = 0; i < 4; i++) {
        int idx = tid + i * 256;
        int r = idx >> 2, c = idx & 3;
        uint32_t dst = sB + g1_sw(r, c);
        asm volatile("cp.async.cg.shared.global [%0], [%1], 16;\n"
                     :: "r"(dst), "l"(Bg + (size_t)r * DDIM + k0 + c * 8));
    }
    asm volatile("cp.async.commit_group;\n");
}

__global__ __launch_bounds__(256, 1)
void gemm1_mma(const float* __restrict__ x, const float* __restrict__ W2,
               float* __restrict__ out) {
    extern __shared__ __align__(128) char g1sm[];
    uint32_t sb = smem_u32(g1sm);
    int tid = threadIdx.x;
    int warp = tid >> 5, lane = tid & 31;
    int bn = blockIdx.x, bm = blockIdx.y;
    int wm = (warp & 1) * 64;
    int wn = (warp >> 1) * 64;

    const float* xb = x + (size_t)(bm * 128) * DDIM;
    const __nv_bfloat16* Bg = g_w1 + (size_t)(bn * G2_BN) * DDIM;

    int r0 = tid >> 1;
    int hsel = tid & 1;
    int lrow = lane & 15;
    int lsel = lane >> 4;

    float acc[4][8][4];
    #pragma unroll
    for (int i = 0; i < 4; i++)
        #pragma unroll
        for (int j = 0; j < 8; j++)
            #pragma unroll
            for (int r = 0; r < 4; r++) acc[i][j][r] = 0.f;

    g2_stage_B(sb + 0 * G2_BBYTES, Bg, 0, tid);
    g2_stage_B(sb + 1 * G2_BBYTES, Bg, G2_BK, tid);
    float4 xv[4];
    #pragma unroll
    for (int i = 0; i < 4; i++)
        xv[i] = *(const float4*)&xb[(size_t)r0 * DDIM + hsel * 16 + i * 4];

    #pragma unroll 1
    for (int c = 0; c < G2_CHUNKS; c++) {
        if (c + 2 < G2_CHUNKS)
            g2_stage_B(sb + ((c + 2) % G2_STAGES) * G2_BBYTES, Bg, (c + 2) * G2_BK, tid);

        {
            uint32_t sA = sb + G2_A_OFF + (c & 1) * G2_ABYTES;
            __align__(16) __nv_bfloat16 ob[16];
            #pragma unroll
            for (int i = 0; i < 4; i++) {
                __nv_bfloat162 p0 = __floats2bfloat162_rn(xv[i].x, xv[i].y);
                __nv_bfloat162 p1 = __floats2bfloat162_rn(xv[i].z, xv[i].w);
                *(uint32_t*)&ob[i * 4]     = *(uint32_t*)&p0;
                *(uint32_t*)&ob[i * 4 + 2] = *(uint32_t*)&p1;
            }
            #pragma unroll
            for (int j = 0; j < 2; j++) {
                uint32_t dst = sA + g1_sw((uint32_t)r0, (uint32_t)(hsel * 2 + j));
                *(uint4*)(g1sm + (dst - sb)) = *(uint4*)&ob[j * 8];
            }
        }

        if (c + 1 < G2_CHUNKS) {
            #pragma unroll
            for (int i = 0; i < 4; i++)
                xv[i] = *(const float4*)&xb[(size_t)r0 * DDIM + (c + 1) * G2_BK + hsel * 16 + i * 4];
        }

        if (c + 2 < G2_CHUNKS) {
            asm volatile("cp.async.wait_group 2;\n");
        } else if (c + 2 == G2_CHUNKS) {
            asm volatile("cp.async.wait_group 1;\n");
        } else {
            asm volatile("cp.async.wait_group 0;\n");
        }
        __syncthreads();

        uint32_t sA = sb + G2_A_OFF + (c & 1) * G2_ABYTES;
        uint32_t sB = sb + (c % G2_STAGES) * G2_BBYTES;

        #pragma unroll
        for (int ks = 0; ks < 2; ks++) {
            uint32_t af[4][4], bf[8][2];
            #pragma unroll
            for (int i = 0; i < 4; i++) {
                uint32_t r = (uint32_t)(wm + i * 16 + lrow);
                ldsm_x4(af[i][0], af[i][1], af[i][2], af[i][3],
                        sA + g1_sw(r, (uint32_t)(ks * 2 + lsel)));
            }
            #pragma unroll
            for (int jb = 0; jb < 4; jb++) {
                uint32_t r = (uint32_t)(wn + jb * 16 + lrow);
                uint32_t q0, q1, q2, q3;
                ldsm_x4(q0, q1, q2, q3, sB + g1_sw(r, (uint32_t)(ks * 2 + lsel)));
                bf[jb * 2][0] = q0;     bf[jb * 2][1] = q2;
                bf[jb * 2 + 1][0] = q1; bf[jb * 2 + 1][1] = q3;
            }
            #pragma unroll
            for (int i = 0; i < 4; i++)
                #pragma unroll
                for (int j = 0; j < 8; j++)
                    MMA_BF16(acc[i][j], af[i], bf[j][0], bf[j][1]);
        }
        __syncthreads();
    }

    float part0[4] = {0.f, 0.f, 0.f, 0.f};
    float part1[4] = {0.f, 0.f, 0.f, 0.f};
    float rs0[4], rm0[4], rs1[4], rm1[4];
    #pragma unroll
    for (int i = 0; i < 4; i++) {
        int m0 = bm * 128 + wm + i * 16 + (lane >> 2);
        rs0[i] = g_rstd[m0];     rm0[i] = rs0[i] * g_mu[m0];
        rs1[i] = g_rstd[m0 + 8]; rm1[i] = rs1[i] * g_mu[m0 + 8];
    }
    #pragma unroll
    for (int j = 0; j < 8; j++) {
        int n = bn * G2_BN + wn + j * 8 + (lane & 3) * 2;
        float2 c1 = *(const float2*)&g_c1[n];
        float2 c2 = *(const float2*)&g_c2[n];
        float2 w2 = *(const float2*)&W2[n];
        #pragma unroll
        for (int i = 0; i < 4; i++) {
            float h00 = rs0[i] * acc[i][j][0] - rm0[i] * c1.x + c2.x;
            float h01 = rs0[i] * acc[i][j][1] - rm0[i] * c1.y + c2.y;
            float h10 = rs1[i] * acc[i][j][2] - rm1[i] * c1.x + c2.x;
            float h11 = rs1[i] * acc[i][j][3] - rm1[i] * c1.y + c2.y;
            part0[i] += gelu_exact(h00) * w2.x + gelu_exact(h01) * w2.y;
            part1[i] += gelu_exact(h10) * w2.x + gelu_exact(h11) * w2.y;
        }
    }
    #pragma unroll
    for (int i = 0; i < 4; i++) {
        part0[i] += __shfl_xor_sync(0xffffffffu, part0[i], 1);
        part0[i] += __shfl_xor_sync(0xffffffffu, part0[i], 2);
        part1[i] += __shfl_xor_sync(0xffffffffu, part1[i], 1);
        part1[i] += __shfl_xor_sync(0xffffffffu, part1[i], 2);
    }
    if ((lane & 3) == 0) {
        int mbase = bm * 128 + wm + (lane >> 2);
        #pragma unroll
        for (int i = 0; i < 4; i++) {
            atomicAdd(&g_diffpre[mbase + i * 16], part0[i]);
            atomicAdd(&g_diffpre[mbase + i * 16 + 8], part1[i]);
        }
    }

    // ---- last bn-CTA of this bm: inline finalize for tokens [bm*128, +128) ----
    __shared__ int slast;
    __threadfence();
    __syncthreads();
    if (tid == 0) slast = (atomicAdd(&g_bmcnt[bm], 1) == 3);
    __syncthreads();
    if (!slast) return;

    float* simp = (float*)g1sm;
    {
        float2 lgv[16]; float dpv[16];
        int t0 = bm * 128 + warp * 16;
        #pragma unroll
        for (int k = 0; k < 16; k++) {
            lgv[k] = *(const float2*)&g_logits[(size_t)(t0 + k) * NEXP + lane * 2];
            dpv[k] = g_diffpre[t0 + k];
        }

        float pimp0 = 0.f, pimp1 = 0.f;
        #pragma unroll
        for (int k = 0; k < 16; k++) {
            int t = t0 + k;
            float diff = 1.f / (1.f + __expf(-dpv[k]));
            float rden = 1.f / (1.f + diff);
            float l0 = lgv[k].x * rden;
            float l1 = lgv[k].y * rden;

            float e0 = __expf(l0), e1 = __expf(l1);
            float sum = e0 + e1;

            float v1, v2; int i1, i2;
            if (l1 > l0) { v1 = l1; i1 = lane * 2 + 1; v2 = l0; i2 = lane * 2; }
            else         { v1 = l0; i1 = lane * 2;     v2 = l1; i2 = lane * 2 + 1; }

            #pragma unroll
            for (int off = 16; off; off >>= 1) {
                sum += __shfl_xor_sync(0xffffffffu, sum, off);
                float qv1 = __shfl_xor_sync(0xffffffffu, v1, off);
                float qv2 = __shfl_xor_sync(0xffffffffu, v2, off);
                int   qi1 = __shfl_xor_sync(0xffffffffu, i1, off);
                int   qi2 = __shfl_xor_sync(0xffffffffu, i2, off);
                bool pf = (v1 > qv1) || (v1 == qv1 && i1 < qi1);
                float cv = pf ? qv1 : v1;  int ci = pf ? qi1 : i1;
                float sv = pf ? v2  : qv2; int si = pf ? i2  : qi2;
                if (!pf) { v1 = qv1; i1 = qi1; }
                bool s2 = (sv > cv) || (sv == cv && si < ci);
                v2 = s2 ? sv : cv; i2 = s2 ? si : ci;
            }

            float inv = 1.f / sum;
            float p0 = e0 * inv, p1 = e1 * inv;
            *(float2*)&out[OFF_P + (size_t)t * NEXP + lane * 2] = make_float2(p0, p1);
            pimp0 += p0; pimp1 += p1;

            float pt1 = __expf(v1) * inv;
            float pt2 = __expf(v2) * inv;
            float s1 = (1.0f - pt1) + pt1;
            float s2v = (1.0f - pt2) + pt2;
            float dsum = fmaxf(s1 + s2v, 1e-9f);

            if (lane == 0) {
                out[OFF_IDX + t * 2]     = (float)i1;
                out[OFF_IDX + t * 2 + 1] = (float)i2;
                out[OFF_SC + t * 2]      = s1 / dsum;
                out[OFF_SC + t * 2 + 1]  = s2v / dsum;
                atomicAdd(&g_loadcnt[i1], 1);
                atomicAdd(&g_loadcnt[i2], 1);
            }
        }

        simp[warp * 64 + lane * 2]     = pimp0;
        simp[warp * 64 + lane * 2 + 1] = pimp1;
    }
    __syncthreads();
    if (tid < 64) {
        float a = 0.f;
        #pragma unroll
        for (int w = 0; w < 8; w++) a += simp[w * 64 + tid];
        atomicAdd(&g_imp[tid], a);
    }

    __shared__ int slast2;
    __threadfence();
    __syncthreads();
    if (tid == 0) slast2 = (atomicAdd(&g_fincnt, 1) == TOKENS / 128 - 1);
    __syncthreads();
    if (slast2 && tid < 64) {
        __threadfence();
        out[OFF_IMP + tid]  = g_imp[tid] * (1.f / TOKENS);
        out[OFF_LOAD + tid] = (float)g_loadcnt[tid] * (1.f / TOKENS);
    }
}

// ---------------- launch ----------------
extern "C" void kernel_launch(void* const* d_in, const int* in_sizes, int n_in,
                              void* d_out, int out_size) {
    const float* x     = (const float*)d_in[0];
    const float* Wg    = (const float*)d_in[1];
    const float* gamma = (const float*)d_in[2];
    const float* beta  = (const float*)d_in[3];
    const float* W1    = (const float*)d_in[4];
    const float* W2    = (const float*)d_in[5];
    float* out = (float*)d_out;

    cudaFuncSetAttribute(gemm1_mma, cudaFuncAttributeMaxDynamicSharedMemorySize, G2_SMEM);
    cudaFuncSetAttribute(ln_logits, cudaFuncAttributeMaxDynamicSharedMemorySize, LN_SMEM);

    prep_kernel<<<(NEXP * DDIM) / 256, 256>>>(Wg);
    ln_logits<<<512, 256, LN_SMEM>>>(x, W1, gamma, beta);
    dim3 g3(HDIM / G2_BN, TOKENS / 128);
    gemm1_mma<<<g3, 256, G2_SMEM>>>(x, W2, out);
}